// round 14
// baseline (speedup 1.0000x reference)
#include <cuda_runtime.h>
#include <cuda_bf16.h>
#include <math.h>
#include <stdint.h>

// Problem constants
#define D_DIM   1024
#define S_LEN   4096
#define B_SZ    2
#define A_DIM   64
#define DI_DIM  4096
#define TOPK    32
#define NROWS   (B_SZ * S_LEN)                 // 8192
#define ROWELEMS ((long)NROWS * D_DIM)         // 8,388,608

#define NEG_INF (-3.402823466e38f)

// ---------------------------------------------------------------------------
// Scratch layout (float offsets; bf16 arrays overlay pairs of floats)
// ---------------------------------------------------------------------------
static const long O_HF   = 0L;
static const long O_VTM  = 8388608L;
static const long O_RTM  = 16777216L;
static const long O_VV   = 25165824L;
static const long O_X2   = 33554432L;
static const long O_R2   = 41943040L;
static const long O_Q    = 50331648L;   // 524288 fp32
static const long O_K    = 50855936L;   // 524288 fp32
static const long O_WQKF = 51380224L;   // 131072 fp32 (concat q/k weights)
static const long O_SC   = 51511296L;   // 33554432 fp32
// bf16 arrays (float-offset; each float slot holds 2 bf16)
static const long O_BHB = 85065728L;
static const long O_BHL = 89260032L;
static const long O_XVH = 93454336L;
static const long O_XVL = 97648640L;
static const long O_XRH = 101842944L;
static const long O_XRL = 106037248L;
static const long O_ATH = 110231552L;
static const long O_ATL = 114425856L;
static const long O_RKH = 118620160L;
static const long O_RKL = 122814464L;
static const long O_KCH = 127008768L;
static const long O_KCL = 143785984L;
static const long O_WB  = 160563200L;
static const long O_WTMV = O_WB;
static const long O_WTMR = O_WTMV + 1048576L;
static const long O_WSAV = O_WTMR + 1048576L;
static const long O_WSAO = O_WSAV + 1048576L;
static const long O_WTMO = O_WSAO + 1048576L;
static const long O_WCMR = O_WTMO + 1048576L;
static const long O_WCMK = O_WCMR + 1048576L;
static const long O_WCMV = O_WCMK + 4194304L;
// end = O_WCMV + 4194304 = 175243264

__device__ __align__(16) float g_scratch[175243264];

// ===========================================================================
// helpers
// ===========================================================================
__device__ __forceinline__ uint32_t smem_u32(const void* p) {
    uint32_t a;
    asm("{ .reg .u64 t; cvta.to.shared.u64 t, %1; cvt.u32.u64 %0, t; }"
        : "=r"(a) : "l"(p));
    return a;
}
__device__ __forceinline__ uint32_t f2tf32(float x) {
    uint32_t r;
    asm("cvt.rna.tf32.f32 %0, %1;" : "=r"(r) : "f"(x));
    return r;
}
__device__ __forceinline__ void split_tf32(uint32_t xbits, uint32_t& hi, uint32_t& lo) {
    float x = __uint_as_float(xbits);
    hi = f2tf32(x);
    lo = f2tf32(x - __uint_as_float(hi));
}
__device__ __forceinline__ float sigmoidf_(float x) { return 1.f / (1.f + expf(-x)); }

__device__ __forceinline__ void cp16(uint32_t s, const void* g) {
    asm volatile("cp.async.cg.shared.global [%0], [%1], 16;" :: "r"(s), "l"(g));
}

// scalar bf16 hi/lo split store
__device__ __forceinline__ void bsplit_store(__nv_bfloat16* H, __nv_bfloat16* L,
                                             long i, float v) {
    __nv_bfloat16 h = __float2bfloat16(v);
    H[i] = h;
    L[i] = __float2bfloat16(v - __bfloat162float(h));
}
__device__ __forceinline__ void bpair_store(__nv_bfloat16* H, __nv_bfloat16* L,
                                            long idx, float vx, float vy) {
    __nv_bfloat16 hx = __float2bfloat16(vx);
    __nv_bfloat16 hy = __float2bfloat16(vy);
    __nv_bfloat16 lx = __float2bfloat16(vx - __bfloat162float(hx));
    __nv_bfloat16 ly = __float2bfloat16(vy - __bfloat162float(hy));
    __nv_bfloat162 hp; hp.x = hx; hp.y = hy;
    __nv_bfloat162 lp; lp.x = lx; lp.y = ly;
    *(__nv_bfloat162*)(H + idx) = hp;
    *(__nv_bfloat162*)(L + idx) = lp;
}

__device__ __forceinline__ void mma1688(float* c, const uint32_t* a, const uint32_t* b) {
    asm volatile(
        "mma.sync.aligned.m16n8k8.row.col.f32.tf32.tf32.f32 "
        "{%0,%1,%2,%3}, {%4,%5,%6,%7}, {%8,%9}, {%0,%1,%2,%3};"
        : "+f"(c[0]), "+f"(c[1]), "+f"(c[2]), "+f"(c[3])
        : "r"(a[0]), "r"(a[1]), "r"(a[2]), "r"(a[3]), "r"(b[0]), "r"(b[1]));
}
__device__ __forceinline__ void mma16816(float* c, const uint32_t* a, const uint32_t* b) {
    asm volatile(
        "mma.sync.aligned.m16n8k16.row.col.f32.bf16.bf16.f32 "
        "{%0,%1,%2,%3}, {%4,%5,%6,%7}, {%8,%9}, {%0,%1,%2,%3};"
        : "+f"(c[0]), "+f"(c[1]), "+f"(c[2]), "+f"(c[3])
        : "r"(a[0]), "r"(a[1]), "r"(a[2]), "r"(a[3]), "r"(b[0]), "r"(b[1]));
}
__device__ __forceinline__ void ldm_x4(uint32_t* r, uint32_t a) {
    asm volatile("ldmatrix.sync.aligned.m8n8.x4.shared.b16 {%0,%1,%2,%3}, [%4];"
        : "=r"(r[0]), "=r"(r[1]), "=r"(r[2]), "=r"(r[3]) : "r"(a));
}

// ===========================================================================
// bf16x3 GEMM (NT): C = (Ah+Al)(Bh+Bl)^T via al*bh + ah*bl + ah*bh
// Term loop hoisted OUTSIDE mf/nf so consecutive MMAs hit independent
// accumulators (per-acc addition order unchanged -> bit-identical results).
// BM=BN=128, BK=32 bf16, 3-stage cp.async, single-sync pipeline, 256 thr.
// MODE 0 supports a TRIPLE merged launch via blockIdx.z (sets 1/2/3).
// MODE 6: blockIdx.x<32 -> Kc (relu^2, bf16 pair), else -> R2 (fp32).
// ===========================================================================
#define BTILE 8192                    // 128*32*2
#define BSTG  (4 * BTILE)             // 32768
#define BNSTG 3
#define BF_DSMEM (BNSTG * BSTG + 128) // 98432

__device__ __forceinline__ void load_stage_bf(
    uint32_t sbase, int stage,
    const __nv_bfloat16* __restrict__ Ah, const __nv_bfloat16* __restrict__ Al,
    const __nv_bfloat16* __restrict__ Bh, const __nv_bfloat16* __restrict__ Bl,
    int bm, int bn, int k0, int K, int tid)
{
    uint32_t s = sbase + stage * BSTG;
#pragma unroll
    for (int j = 0; j < 2; j++) {
        int gi = tid + j * 256;        // 0..511
        int row = gi >> 2, g = gi & 3;
        uint32_t so = (uint32_t)(row * 64 + ((g ^ ((row >> 1) & 3)) << 4));
        long ao = (long)(bm + row) * K + k0 + g * 8;
        long bo = (long)(bn + row) * K + k0 + g * 8;
        cp16(s + so,             Ah + ao);
        cp16(s + BTILE + so,     Al + ao);
        cp16(s + 2 * BTILE + so, Bh + bo);
        cp16(s + 3 * BTILE + so, Bl + bo);
    }
}

template<int MODE>
__global__ void __launch_bounds__(256, 2) gemm_bf(
    const __nv_bfloat16* __restrict__ Ah, const __nv_bfloat16* __restrict__ Al,
    const __nv_bfloat16* __restrict__ Bh, const __nv_bfloat16* __restrict__ Bl,
    const float* __restrict__ bias1,
    const float* __restrict__ ex1, const float* __restrict__ ex2,
    float* __restrict__ Of,
    __nv_bfloat16* __restrict__ Oh, __nv_bfloat16* __restrict__ Ol,
    int M, int N, int K,
    const __nv_bfloat16* A2h, const __nv_bfloat16* A2l,
    const __nv_bfloat16* B2h, const __nv_bfloat16* B2l, float* Of2,
    const __nv_bfloat16* A3h, const __nv_bfloat16* A3l,
    const __nv_bfloat16* B3h, const __nv_bfloat16* B3l, float* Of3,
    const float* bias3)
{
    extern __shared__ __align__(16) char dsm[];

    bool second = false;   // MODE 6: R2 sub-launch
    int bn;
    if (MODE == 0) {
        if (blockIdx.z == 1) { Ah = A2h; Al = A2l; Bh = B2h; Bl = B2l; Of = Of2; }
        else if (blockIdx.z == 2) {
            Ah = A3h; Al = A3l; Bh = B3h; Bl = B3l; Of = Of3; bias1 = bias3;
        }
        bn = blockIdx.x * 128;
    } else if (MODE == 6) {
        if (blockIdx.x < 32) {
            bn = blockIdx.x * 128;            // Kc path, N stays 4096
        } else {
            second = true;
            Ah = A2h; Al = A2l; Bh = B2h; Bl = B2l;
            N = 1024;
            bn = (blockIdx.x - 32) * 128;     // R2 path
        }
    } else {
        bn = blockIdx.x * 128;
    }

    const int tid  = threadIdx.x;
    const int wid  = tid >> 5;
    const int lane = tid & 31;
    const int wm   = wid & 1;
    const int wn   = wid >> 1;
    const int bm = blockIdx.y * 128;
    const int KT = K / 32;
    const int lr = lane >> 2, lk = lane & 3;

    float acc[4][4][4];
#pragma unroll
    for (int i = 0; i < 4; i++)
#pragma unroll
        for (int j = 0; j < 4; j++)
#pragma unroll
            for (int r = 0; r < 4; r++) acc[i][j][r] = 0.f;

    // ldmatrix per-lane swizzled base offsets (granule bit from lane>>4)
    uint32_t offA[4], offB[2];
    {
        int ga = (lane >> 4) & 1;
        int rb = wm * 64 + (lane & 15);
#pragma unroll
        for (int mf = 0; mf < 4; mf++) {
            int row = rb + mf * 16;
            offA[mf] = (uint32_t)(row * 64 + ((ga ^ ((row >> 1) & 3)) << 4));
        }
#pragma unroll
        for (int pg = 0; pg < 2; pg++) {
            int row = wn * 32 + pg * 16 + (lane & 15);
            offB[pg] = (uint32_t)(row * 64 + ((ga ^ ((row >> 1) & 3)) << 4)) + 2 * BTILE;
        }
    }

    uint32_t sbase = (smem_u32(dsm) + 127u) & ~127u;
    load_stage_bf(sbase, 0, Ah, Al, Bh, Bl, bm, bn, 0, K, tid);
    asm volatile("cp.async.commit_group;" ::: "memory");
    load_stage_bf(sbase, 1, Ah, Al, Bh, Bl, bm, bn, 32, K, tid);
    asm volatile("cp.async.commit_group;" ::: "memory");

    int stage = 0;
    for (int kt = 0; kt < KT; kt++) {
        asm volatile("cp.async.wait_group 1;" ::: "memory");
        __syncthreads();   // also orders kt-1 MMAs before overwriting stage kt+2

        int ps = kt + 2;
        if (ps < KT) {
            int pstage = stage + 2; if (pstage >= BNSTG) pstage -= BNSTG;
            load_stage_bf(sbase, pstage, Ah, Al, Bh, Bl, bm, bn, ps * 32, K, tid);
        }
        asm volatile("cp.async.commit_group;" ::: "memory");

        uint32_t st = sbase + stage * BSTG;

#pragma unroll
        for (int ks = 0; ks < 2; ks++) {
            uint32_t kx = (uint32_t)(ks << 5);
            uint32_t tb0[4], tl0[4], tb1[4], tl1[4];
            ldm_x4(tb0, (st + offB[0]) ^ kx);
            ldm_x4(tl0, (st + offB[0] + BTILE) ^ kx);
            ldm_x4(tb1, (st + offB[1]) ^ kx);
            ldm_x4(tl1, (st + offB[1] + BTILE) ^ kx);
            uint32_t ah[4][4], al[4][4];
#pragma unroll
            for (int mf = 0; mf < 4; mf++) {
                ldm_x4(ah[mf], (st + offA[mf]) ^ kx);
                ldm_x4(al[mf], (st + offA[mf] + BTILE) ^ kx);
            }
            uint32_t b_h[4][2] = {{tb0[0],tb0[2]},{tb0[1],tb0[3]},
                                  {tb1[0],tb1[2]},{tb1[1],tb1[3]}};
            uint32_t b_l[4][2] = {{tl0[0],tl0[2]},{tl0[1],tl0[3]},
                                  {tl1[0],tl1[2]},{tl1[1],tl1[3]}};
            // term 1: al*bh — 16 independent accumulators back-to-back
#pragma unroll
            for (int mf = 0; mf < 4; mf++)
#pragma unroll
                for (int nf = 0; nf < 4; nf++)
                    mma16816(acc[mf][nf], al[mf], b_h[nf]);
            // term 2: ah*bl
#pragma unroll
            for (int mf = 0; mf < 4; mf++)
#pragma unroll
                for (int nf = 0; nf < 4; nf++)
                    mma16816(acc[mf][nf], ah[mf], b_l[nf]);
            // term 3: ah*bh
#pragma unroll
            for (int mf = 0; mf < 4; mf++)
#pragma unroll
                for (int nf = 0; nf < 4; nf++)
                    mma16816(acc[mf][nf], ah[mf], b_h[nf]);
        }
        stage++; if (stage >= BNSTG) stage = 0;
    }

    // epilogue
#pragma unroll
    for (int mf = 0; mf < 4; mf++) {
        int r0 = bm + wm * 64 + mf * 16 + lr;
#pragma unroll
        for (int nf = 0; nf < 4; nf++) {
            int c0 = bn + wn * 32 + nf * 8 + lk * 2;
#pragma unroll
            for (int h = 0; h < 2; h++) {
                int row = r0 + h * 8;
                long idx = (long)row * N + c0;
                float vx = acc[mf][nf][2 * h + 0];
                float vy = acc[mf][nf][2 * h + 1];
                if (MODE == 0) {
                    if (bias1) { vx += bias1[c0]; vy += bias1[c0 + 1]; }
                    *(float2*)(Of + idx) = make_float2(vx, vy);
                } else if (MODE == 1) {
                    vx = fmaxf(vx, 0.f); vx *= vx;
                    vy = fmaxf(vy, 0.f); vy *= vy;
                    bpair_store(Oh, Ol, idx, vx, vy);
                } else if (MODE == 3) {
                    vx += bias1[c0]; vy += bias1[c0 + 1];
                    float rx = sigmoidf_(ex1[idx])     * (vx + ex2[idx]);
                    float ry = sigmoidf_(ex1[idx + 1]) * (vy + ex2[idx + 1]);
                    bpair_store(Oh, Ol, idx, rx, ry);
                } else if (MODE == 4) {
                    *(float2*)(Of + idx) = make_float2(ex1[idx] + vx, ex1[idx + 1] + vy);
                } else if (MODE == 5) {
                    float rx = ex1[idx]     + sigmoidf_(ex2[idx])     * vx;
                    float ry = ex1[idx + 1] + sigmoidf_(ex2[idx + 1]) * vy;
                    *(float2*)(Of + idx) = make_float2(rx, ry);
                } else { // MODE 6
                    if (!second) {
                        vx = fmaxf(vx, 0.f); vx *= vx;
                        vy = fmaxf(vy, 0.f); vy *= vy;
                        bpair_store(Oh, Ol, idx, vx, vy);
                    } else {
                        *(float2*)(Of2 + idx) = make_float2(vx, vy);
                    }
                }
            }
        }
    }
}

// ===========================================================================
// tf32x3 GEMM (NT) with in-kernel split (fp32 inputs) — precision path.
// Same dependency-interleaving of the 3 terms.
// ===========================================================================
#define TBKF 16
#define T_A_BYTES (128 * TBKF * 4)      // 8192
#define T_STG     (2 * T_A_BYTES)       // 16384
#define TNSTG 4
#define TF_DSMEM (TNSTG * T_STG)        // 65536

__device__ __forceinline__ uint32_t lde(const uint32_t* t, int row, int k) {
    int g = k >> 2;
    return t[row * 16 + (((g ^ ((row >> 1) & 3)) << 2) | (k & 3))];
}

__device__ __forceinline__ void load_stage_tf(
    uint32_t sbase, int stage, const float* __restrict__ A,
    const float* __restrict__ B, int bm, int bn, int k0, int K, int tid)
{
    uint32_t sa = sbase + stage * T_STG;
    uint32_t sb = sa + T_A_BYTES;
    int row = tid >> 1;
    int g0 = (tid & 1) * 2;
#pragma unroll
    for (int j = 0; j < 2; j++) {
        int g = g0 + j;
        uint32_t so = (uint32_t)(row * 64 + ((g ^ ((row >> 1) & 3)) << 4));
        cp16(sa + so, A + (long)(bm + row) * K + k0 + g * 4);
        cp16(sb + so, B + (long)(bn + row) * K + k0 + g * 4);
    }
}

template<int MODE>
__global__ void __launch_bounds__(256) gemm_tf(
    const float* __restrict__ A, const float* __restrict__ B,
    const float* __restrict__ qb, const float* __restrict__ kb,
    float* __restrict__ O1, float* __restrict__ Qf, float* __restrict__ Kf,
    int M, int N, int K, float alpha, long sA, long sB, long sC)
{
    extern __shared__ __align__(16) char dsm[];

    A += (long)blockIdx.z * sA;
    B += (long)blockIdx.z * sB;
    O1 += (long)blockIdx.z * sC;

    const int tid  = threadIdx.x;
    const int wid  = tid >> 5;
    const int lane = tid & 31;
    const int wm   = wid & 1;
    const int wn   = wid >> 1;
    const int bm = blockIdx.y * 128;
    const int bn = blockIdx.x * 128;
    const int KT = K / TBKF;

    uint32_t sbase = smem_u32(dsm);

    float acc[4][4][4];
#pragma unroll
    for (int i = 0; i < 4; i++)
#pragma unroll
        for (int j = 0; j < 4; j++)
#pragma unroll
            for (int r = 0; r < 4; r++) acc[i][j][r] = 0.f;

#pragma unroll
    for (int s = 0; s < TNSTG - 1; s++) {
        if (s < KT) load_stage_tf(sbase, s, A, B, bm, bn, s * TBKF, K, tid);
        asm volatile("cp.async.commit_group;" ::: "memory");
    }

    const int lr = lane >> 2;
    const int lk = lane & 3;

    for (int kt = 0; kt < KT; kt++) {
        __syncthreads();
        if (kt + 3 < KT)
            load_stage_tf(sbase, (kt + 3) & 3, A, B, bm, bn, (kt + 3) * TBKF, K, tid);
        asm volatile("cp.async.commit_group;" ::: "memory");
        asm volatile("cp.async.wait_group 3;" ::: "memory");
        __syncthreads();

        const uint32_t* sa = (const uint32_t*)(dsm + (size_t)(kt & 3) * T_STG);
        const uint32_t* sb = sa + 128 * TBKF;

#pragma unroll
        for (int ks = 0; ks < 2; ks++) {
            int kbase = ks * 8;
            uint32_t ah[4][4], al[4][4], bh[4][2], bl[4][2];
#pragma unroll
            for (int mf = 0; mf < 4; mf++) {
                int r0 = wm * 64 + mf * 16 + lr;
                split_tf32(lde(sa, r0,     kbase + lk),     ah[mf][0], al[mf][0]);
                split_tf32(lde(sa, r0 + 8, kbase + lk),     ah[mf][1], al[mf][1]);
                split_tf32(lde(sa, r0,     kbase + lk + 4), ah[mf][2], al[mf][2]);
                split_tf32(lde(sa, r0 + 8, kbase + lk + 4), ah[mf][3], al[mf][3]);
            }
#pragma unroll
            for (int nf = 0; nf < 4; nf++) {
                int n0 = wn * 32 + nf * 8 + lr;
                split_tf32(lde(sb, n0, kbase + lk),     bh[nf][0], bl[nf][0]);
                split_tf32(lde(sb, n0, kbase + lk + 4), bh[nf][1], bl[nf][1]);
            }
#pragma unroll
            for (int mf = 0; mf < 4; mf++)
#pragma unroll
                for (int nf = 0; nf < 4; nf++)
                    mma1688(acc[mf][nf], al[mf], bh[nf]);
#pragma unroll
            for (int mf = 0; mf < 4; mf++)
#pragma unroll
                for (int nf = 0; nf < 4; nf++)
                    mma1688(acc[mf][nf], ah[mf], bl[nf]);
#pragma unroll
            for (int mf = 0; mf < 4; mf++)
#pragma unroll
                for (int nf = 0; nf < 4; nf++)
                    mma1688(acc[mf][nf], ah[mf], bh[nf]);
        }
    }

#pragma unroll
    for (int mf = 0; mf < 4; mf++) {
        int r0 = bm + wm * 64 + mf * 16 + lr;
#pragma unroll
        for (int nf = 0; nf < 4; nf++) {
            int c0 = bn + wn * 32 + nf * 8 + lk * 2;
#pragma unroll
            for (int h = 0; h < 2; h++) {
                int row = r0 + h * 8;
                float vx = acc[mf][nf][2 * h + 0] * alpha;
                float vy = acc[mf][nf][2 * h + 1] * alpha;
                if (MODE == 0) {
                    *(float2*)(O1 + (long)row * N + c0) = make_float2(vx, vy);
                } else { // MODE 2: Q||K
                    if (c0 < 64) {
                        vx += qb[c0]; vy += qb[c0 + 1];
                        *(float2*)(Qf + (long)row * 64 + c0) = make_float2(vx, vy);
                    } else {
                        vx += kb[c0 - 64]; vy += kb[c0 - 63];
                        *(float2*)(Kf + (long)row * 64 + c0 - 64) = make_float2(vx, vy);
                    }
                }
            }
        }
    }
}

// ---------------------------------------------------------------------------
// Weight splits: fp32 -> bf16 hi/lo, one fused launch (8 jobs, guarded)
// ---------------------------------------------------------------------------
struct SplitJob { const float* src; __nv_bfloat16* h; __nv_bfloat16* l; long n; };
struct SplitJobs8 { SplitJob j[8]; };

__global__ void __launch_bounds__(256) split8(SplitJobs8 jobs)
{
    const SplitJob jb = jobs.j[blockIdx.y];
    long i = ((long)blockIdx.x * 256 + threadIdx.x) * 2;
    if (i < jb.n) bpair_store(jb.h, jb.l, i, jb.src[i], jb.src[i + 1]);
}

__global__ void __launch_bounds__(256) concat_qk(
    const float* __restrict__ q, const float* __restrict__ k, float* __restrict__ o)
{
    int i = blockIdx.x * 256 + threadIdx.x;   // n = 131072
    o[i] = (i < 65536) ? q[i] : k[i - 65536];
}

// ---------------------------------------------------------------------------
// Fused RMSNorm + token-shift mixing.
// ---------------------------------------------------------------------------
template<int WRITE_H>
__global__ void __launch_bounds__(256) norm_mix_kernel(
    const float* __restrict__ x, const float* __restrict__ w,
    const float* __restrict__ mA, const float* __restrict__ mB,
    __nv_bfloat16* __restrict__ oAh, __nv_bfloat16* __restrict__ oAl,
    __nv_bfloat16* __restrict__ oBh, __nv_bfloat16* __restrict__ oBl,
    float* __restrict__ hF, __nv_bfloat16* __restrict__ hbH,
    __nv_bfloat16* __restrict__ hbL)
{
    long row = blockIdx.x;
    long prev = ((row & (S_LEN - 1)) == 0) ? row : row - 1;
    int tid = threadIdx.x;
    const float* xc = x + row * D_DIM;
    const float* xp = x + prev * D_DIM;

    float c[4], p[4];
    float sc_ = 0.f, sp_ = 0.f;
#pragma unroll
    for (int d = 0; d < 4; d++) {
        c[d] = xc[tid + d * 256];
        p[d] = xp[tid + d * 256];
        sc_ += c[d] * c[d];
        sp_ += p[d] * p[d];
    }
#pragma unroll
    for (int o = 16; o > 0; o >>= 1) {
        sc_ += __shfl_xor_sync(0xffffffffu, sc_, o);
        sp_ += __shfl_xor_sync(0xffffffffu, sp_, o);
    }

    __shared__ float redc[8], redp[8];
    __shared__ float s_invc, s_invp;
    if ((tid & 31) == 0) { redc[tid >> 5] = sc_; redp[tid >> 5] = sp_; }
    __syncthreads();
    if (tid == 0) {
        float tc = 0.f, tp = 0.f;
#pragma unroll
        for (int i = 0; i < 8; i++) { tc += redc[i]; tp += redp[i]; }
        s_invc = 1.0f / (sqrtf(tc / (float)D_DIM) + 1e-8f);
        s_invp = 1.0f / (sqrtf(tp / (float)D_DIM) + 1e-8f);
    }
    __syncthreads();
    float invc = s_invc, invp = s_invp;

#pragma unroll
    for (int d = 0; d < 4; d++) {
        int cc = tid + d * 256;
        long ci = row * D_DIM + cc;
        float nc = w[cc] * c[d] * invc;
        float np = w[cc] * p[d] * invp;
        float a = mA[cc], b = mB[cc];
        bsplit_store(oAh, oAl, ci, nc * a + np * (1.f - a));
        bsplit_store(oBh, oBl, ci, nc * b + np * (1.f - b));
        if (WRITE_H) {
            hF[ci] = nc;
            bsplit_store(hbH, hbL, ci, nc);
        }
    }
}

// ---------------------------------------------------------------------------
// Sparse attention: chunked top-32, softmax, attn@V -> bf16 pair out.
// ---------------------------------------------------------------------------
__global__ void __launch_bounds__(256) sparse_attn_kernel(
    const float* __restrict__ scores, const float* __restrict__ V,
    __nv_bfloat16* __restrict__ oh, __nv_bfloat16* __restrict__ ol)
{
    __shared__ float sc[S_LEN];
    __shared__ float cmax[128];
    __shared__ float selV[TOPK];
    __shared__ int   selI[TOPK];
    __shared__ float wsel[TOPK];

    long row = blockIdx.x;
    long b = row >> 12;
    int tid = threadIdx.x;
    int lane = tid & 31;

    const float* srow = scores + row * S_LEN;
    for (int i = tid; i < S_LEN; i += 256) sc[i] = srow[i];
    __syncthreads();

    if (tid < 128) {
        float m = NEG_INF;
#pragma unroll 8
        for (int i = 0; i < 32; i++) m = fmaxf(m, sc[tid * 32 + i]);
        cmax[tid] = m;
    }
    __syncthreads();

    if (tid < 32) {
        for (int it = 0; it < TOPK; it++) {
            float bv = NEG_INF; int bc = 0;
#pragma unroll
            for (int j = 0; j < 4; j++) {
                int c = lane * 4 + j;
                float v = cmax[c];
                if (v > bv) { bv = v; bc = c; }
            }
#pragma unroll
            for (int o = 16; o > 0; o >>= 1) {
                float ov = __shfl_down_sync(0xffffffffu, bv, o);
                int   oc = __shfl_down_sync(0xffffffffu, bc, o);
                if (ov > bv || (ov == bv && oc < bc)) { bv = ov; bc = oc; }
            }
            bc = __shfl_sync(0xffffffffu, bc, 0);

            float v = sc[bc * 32 + lane];
            float mv = v; int mi = lane;
#pragma unroll
            for (int o = 16; o > 0; o >>= 1) {
                float ov = __shfl_down_sync(0xffffffffu, mv, o);
                int   oi = __shfl_down_sync(0xffffffffu, mi, o);
                if (ov > mv || (ov == mv && oi < mi)) { mv = ov; mi = oi; }
            }
            mv = __shfl_sync(0xffffffffu, mv, 0);
            mi = __shfl_sync(0xffffffffu, mi, 0);

            if (lane == mi) { sc[bc * 32 + lane] = NEG_INF; v = NEG_INF; }
            if (lane == 0) { selV[it] = mv; selI[it] = bc * 32 + mi; }

            float nm = v;
#pragma unroll
            for (int o = 16; o > 0; o >>= 1)
                nm = fmaxf(nm, __shfl_down_sync(0xffffffffu, nm, o));
            if (lane == 0) cmax[bc] = nm;
        }
        float m = __shfl_sync(0xffffffffu, selV[0], 0);
        float e = expf(selV[lane] - m);
        float s = e;
#pragma unroll
        for (int o = 16; o > 0; o >>= 1) s += __shfl_xor_sync(0xffffffffu, s, o);
        wsel[lane] = e / s;
    }
    __syncthreads();

    float acc[4] = {0.f, 0.f, 0.f, 0.f};
    const float* Vb = V + b * (long)S_LEN * D_DIM;
#pragma unroll 1
    for (int j = 0; j < TOPK; j++) {
        float w = wsel[j];
        const float* vr = Vb + (long)selI[j] * D_DIM;
#pragma unroll
        for (int d = 0; d < 4; d++) acc[d] += w * vr[tid + d * 256];
    }
#pragma unroll
    for (int d = 0; d < 4; d++)
        bsplit_store(oh, ol, row * D_DIM + tid + d * 256, acc[d]);
}

// ---------------------------------------------------------------------------
// Host launchers
// ---------------------------------------------------------------------------
typedef __nv_bfloat16 bf16;

static void launch_bf(int mode,
    const bf16* Ah, const bf16* Al, const bf16* Bh, const bf16* Bl,
    const float* b1, const float* e1, const float* e2,
    float* Of, bf16* Oh, bf16* Ol, int M, int N, int K,
    const bf16* A2h = nullptr, const bf16* A2l = nullptr,
    const bf16* B2h = nullptr, const bf16* B2l = nullptr, float* Of2 = nullptr,
    const bf16* A3h = nullptr, const bf16* A3l = nullptr,
    const bf16* B3h = nullptr, const bf16* B3l = nullptr, float* Of3 = nullptr,
    const float* b3 = nullptr, int gx = -1, int gz = 1)
{
    dim3 grid(gx < 0 ? N / 128 : gx, M / 128, gz);
    switch (mode) {
    case 0: gemm_bf<0><<<grid, 256, BF_DSMEM>>>(Ah,Al,Bh,Bl,b1,e1,e2,Of,Oh,Ol,M,N,K,A2h,A2l,B2h,B2l,Of2,A3h,A3l,B3h,B3l,Of3,b3); break;
    case 1: gemm_bf<1><<<grid, 256, BF_DSMEM>>>(Ah,Al,Bh,Bl,b1,e1,e2,Of,Oh,Ol,M,N,K,A2h,A2l,B2h,B2l,Of2,A3h,A3l,B3h,B3l,Of3,b3); break;
    case 3: gemm_bf<3><<<grid, 256, BF_DSMEM>>>(Ah,Al,Bh,Bl,b1,e1,e2,Of,Oh,Ol,M,N,K,A2h,A2l,B2h,B2l,Of2,A3h,A3l,B3h,B3l,Of3,b3); break;
    case 4: gemm_bf<4><<<grid, 256, BF_DSMEM>>>(Ah,Al,Bh,Bl,b1,e1,e2,Of,Oh,Ol,M,N,K,A2h,A2l,B2h,B2l,Of2,A3h,A3l,B3h,B3l,Of3,b3); break;
    case 5: gemm_bf<5><<<grid, 256, BF_DSMEM>>>(Ah,Al,Bh,Bl,b1,e1,e2,Of,Oh,Ol,M,N,K,A2h,A2l,B2h,B2l,Of2,A3h,A3l,B3h,B3l,Of3,b3); break;
    default: gemm_bf<6><<<grid, 256, BF_DSMEM>>>(Ah,Al,Bh,Bl,b1,e1,e2,Of,Oh,Ol,M,N,K,A2h,A2l,B2h,B2l,Of2,A3h,A3l,B3h,B3l,Of3,b3); break;
    }
}

extern "C" void kernel_launch(void* const* d_in, const int* in_sizes, int n_in,
                              void* d_out, int out_size)
{
    const float* x         = (const float*)d_in[0];
    const float* norm1_w   = (const float*)d_in[1];
    const float* tm_mix_v  = (const float*)d_in[3];
    const float* tm_mix_r  = (const float*)d_in[4];
    const float* tm_value_w  = (const float*)d_in[6];
    const float* tm_recept_w = (const float*)d_in[7];
    const float* tm_out_w    = (const float*)d_in[8];
    const float* sa_q_w    = (const float*)d_in[9];
    const float* sa_q_b    = (const float*)d_in[10];
    const float* sa_k_w    = (const float*)d_in[11];
    const float* sa_k_b    = (const float*)d_in[12];
    const float* sa_v_w    = (const float*)d_in[13];
    const float* sa_v_b    = (const float*)d_in[14];
    const float* sa_o_w    = (const float*)d_in[15];
    const float* sa_o_b    = (const float*)d_in[16];
    const float* norm2_w   = (const float*)d_in[17];
    const float* cm_mix_k  = (const float*)d_in[18];
    const float* cm_mix_r  = (const float*)d_in[19];
    const float* cm_key_w    = (const float*)d_in[20];
    const float* cm_recept_w = (const float*)d_in[21];
    const float* cm_value_w  = (const float*)d_in[22];
    float* out = (float*)d_out;

    cudaFuncSetAttribute(gemm_bf<0>, cudaFuncAttributeMaxDynamicSharedMemorySize, BF_DSMEM);
    cudaFuncSetAttribute(gemm_bf<1>, cudaFuncAttributeMaxDynamicSharedMemorySize, BF_DSMEM);
    cudaFuncSetAttribute(gemm_bf<3>, cudaFuncAttributeMaxDynamicSharedMemorySize, BF_DSMEM);
    cudaFuncSetAttribute(gemm_bf<4>, cudaFuncAttributeMaxDynamicSharedMemorySize, BF_DSMEM);
    cudaFuncSetAttribute(gemm_bf<5>, cudaFuncAttributeMaxDynamicSharedMemorySize, BF_DSMEM);
    cudaFuncSetAttribute(gemm_bf<6>, cudaFuncAttributeMaxDynamicSharedMemorySize, BF_DSMEM);
    cudaFuncSetAttribute(gemm_tf<0>, cudaFuncAttributeMaxDynamicSharedMemorySize, TF_DSMEM);
    cudaFuncSetAttribute(gemm_tf<2>, cudaFuncAttributeMaxDynamicSharedMemorySize, TF_DSMEM);

    float* sp = nullptr;
    cudaGetSymbolAddress((void**)&sp, g_scratch);

    float* hF   = sp + O_HF;
    float* Vtm  = sp + O_VTM;
    float* Rtm  = sp + O_RTM;
    float* Vv   = sp + O_VV;
    float* x2   = sp + O_X2;
    float* R2   = sp + O_R2;
    float* Qf   = sp + O_Q;
    float* Kf   = sp + O_K;
    float* wQKf = sp + O_WQKF;
    float* SCo  = sp + O_SC;

    bf16* hbH = (bf16*)(sp + O_BHB); bf16* hbL = (bf16*)(sp + O_BHL);
    bf16* xvH = (bf16*)(sp + O_XVH); bf16* xvL = (bf16*)(sp + O_XVL);
    bf16* xrH = (bf16*)(sp + O_XRH); bf16* xrL = (bf16*)(sp + O_XRL);
    bf16* atH = (bf16*)(sp + O_ATH); bf16* atL = (bf16*)(sp + O_ATL);
    bf16* rkH = (bf16*)(sp + O_RKH); bf16* rkL = (bf16*)(sp + O_RKL);
    bf16* KcH = (bf16*)(sp + O_KCH); bf16* KcL = (bf16*)(sp + O_KCL);

    bf16* wTMVh = (bf16*)(sp + O_WTMV); bf16* wTMVl = wTMVh + 1048576L;
    bf16* wTMRh = (bf16*)(sp + O_WTMR); bf16* wTMRl = wTMRh + 1048576L;
    bf16* wSAVh = (bf16*)(sp + O_WSAV); bf16* wSAVl = wSAVh + 1048576L;
    bf16* wSAOh = (bf16*)(sp + O_WSAO); bf16* wSAOl = wSAOh + 1048576L;
    bf16* wTMOh = (bf16*)(sp + O_WTMO); bf16* wTMOl = wTMOh + 1048576L;
    bf16* wCMRh = (bf16*)(sp + O_WCMR); bf16* wCMRl = wCMRh + 1048576L;
    bf16* wCMKh = (bf16*)(sp + O_WCMK); bf16* wCMKl = wCMKh + 4194304L;
    bf16* wCMVh = (bf16*)(sp + O_WCMV); bf16* wCMVl = wCMVh + 4194304L;

    // one fused weight-split launch (guarded per-job n) + QK concat
    {
        SplitJobs8 s8;
        s8.j[0] = {tm_value_w,  wTMVh, wTMVl, 1048576L};
        s8.j[1] = {tm_recept_w, wTMRh, wTMRl, 1048576L};
        s8.j[2] = {sa_v_w,      wSAVh, wSAVl, 1048576L};
        s8.j[3] = {sa_o_w,      wSAOh, wSAOl, 1048576L};
        s8.j[4] = {tm_out_w,    wTMOh, wTMOl, 1048576L};
        s8.j[5] = {cm_recept_w, wCMRh, wCMRl, 1048576L};
        s8.j[6] = {cm_key_w,    wCMKh, wCMKl, 4194304L};
        s8.j[7] = {cm_value_w,  wCMVh, wCMVl, 4194304L};
        split8<<<dim3(8192, 8, 1), 256>>>(s8);
        concat_qk<<<512, 256>>>(sa_q_w, sa_k_w, wQKf);
    }

    // --- time-mix branch ---
    norm_mix_kernel<1><<<NROWS, 256>>>(x, norm1_w, tm_mix_v, tm_mix_r,
                                       xvH, xvL, xrH, xrL, hF, hbH, hbL);

    // triple merged GEMM: z=0 Vtm, z=1 Rtm, z=2 Vv (bias sa_v_b)
    launch_bf(0, xvH, xvL, wTMVh, wTMVl, nullptr, nullptr, nullptr,
              Vtm, nullptr, nullptr, NROWS, D_DIM, D_DIM,
              xrH, xrL, wTMRh, wTMRl, Rtm,
              hbH, hbL, wSAVh, wSAVl, Vv, sa_v_b, -1, 3);

    // Q||K projection on tf32x3 precision path
    {
        dim3 g(1, NROWS / 128, 1);
        gemm_tf<2><<<g, 256, TF_DSMEM>>>(hF, wQKf, sa_q_b, sa_k_b,
                                         nullptr, Qf, Kf, NROWS, 128, D_DIM,
                                         1.f, 0, 0, 0);
    }

    // scores[b] = (Q[b] @ K[b]^T) / 8 on tf32x3
    {
        dim3 g(S_LEN / 128, S_LEN / 128, B_SZ);
        gemm_tf<0><<<g, 256, TF_DSMEM>>>(Qf, Kf, nullptr, nullptr,
                                         SCo, nullptr, nullptr, S_LEN, S_LEN, A_DIM,
                                         0.125f, (long)S_LEN * A_DIM,
                                         (long)S_LEN * A_DIM, (long)S_LEN * S_LEN);
    }

    sparse_attn_kernel<<<NROWS, 256>>>(SCo, Vv, atH, atL);

    // rkv = sigmoid(Rtm) * (attn@W_o + b_o + Vtm) -> bf16 pair
    launch_bf(3, atH, atL, wSAOh, wSAOl, sa_o_b, Rtm, Vtm,
              nullptr, rkH, rkL, NROWS, D_DIM, D_DIM);

    // x2 = x + rkv @ W_out
    launch_bf(4, rkH, rkL, wTMOh, wTMOl, nullptr, x, nullptr,
              x2, nullptr, nullptr, NROWS, D_DIM, D_DIM);

    // --- channel-mix branch ---
    norm_mix_kernel<0><<<NROWS, 256>>>(x2, norm2_w, cm_mix_k, cm_mix_r,
                                       xvH, xvL, xrH, xrL,
                                       nullptr, nullptr, nullptr);

    // merged: blocks x<32 -> Kc = relu(xk2@W_k)^2 (bf16 pair), x>=32 -> R2
    launch_bf(6, xvH, xvL, wCMKh, wCMKl, nullptr, nullptr, nullptr,
              nullptr, KcH, KcL, NROWS, DI_DIM, D_DIM,
              xrH, xrL, wCMRh, wCMRl, R2,
              nullptr, nullptr, nullptr, nullptr, nullptr, nullptr, 40, 1);

    // out = x2 + sigmoid(R2) * (Kc @ W_v)
    launch_bf(5, KcH, KcL, wCMVh, wCMVl, nullptr, x2, R2,
              out, nullptr, nullptr, NROWS, D_DIM, DI_DIM);
}

// round 15
// speedup vs baseline: 1.0087x; 1.0087x over previous
#include <cuda_runtime.h>
#include <cuda_bf16.h>
#include <math.h>
#include <stdint.h>

// Problem constants
#define D_DIM   1024
#define S_LEN   4096
#define B_SZ    2
#define A_DIM   64
#define DI_DIM  4096
#define TOPK    32
#define NROWS   (B_SZ * S_LEN)                 // 8192
#define ROWELEMS ((long)NROWS * D_DIM)         // 8,388,608

#define NEG_INF (-3.402823466e38f)

// ---------------------------------------------------------------------------
// Scratch layout (float offsets; bf16 arrays overlay pairs of floats)
// ---------------------------------------------------------------------------
static const long O_HF   = 0L;
static const long O_VTM  = 8388608L;
static const long O_RTM  = 16777216L;
static const long O_VV   = 25165824L;
static const long O_X2   = 33554432L;
static const long O_R2   = 41943040L;
static const long O_Q    = 50331648L;   // 524288 fp32
static const long O_K    = 50855936L;   // 524288 fp32
static const long O_WQKF = 51380224L;   // 131072 fp32 (concat q/k weights)
static const long O_SC   = 51511296L;   // 33554432 fp32
// bf16 arrays (float-offset; each float slot holds 2 bf16)
static const long O_BHB = 85065728L;
static const long O_BHL = 89260032L;
static const long O_XVH = 93454336L;
static const long O_XVL = 97648640L;
static const long O_XRH = 101842944L;
static const long O_XRL = 106037248L;
static const long O_ATH = 110231552L;
static const long O_ATL = 114425856L;
static const long O_RKH = 118620160L;
static const long O_RKL = 122814464L;
static const long O_KCH = 127008768L;
static const long O_KCL = 143785984L;
static const long O_WB  = 160563200L;
static const long O_WTMV = O_WB;
static const long O_WTMR = O_WTMV + 1048576L;
static const long O_WSAV = O_WTMR + 1048576L;
static const long O_WSAO = O_WSAV + 1048576L;
static const long O_WTMO = O_WSAO + 1048576L;
static const long O_WCMR = O_WTMO + 1048576L;
static const long O_WCMK = O_WCMR + 1048576L;
static const long O_WCMV = O_WCMK + 4194304L;
// end = O_WCMV + 4194304 = 175243264

__device__ __align__(16) float g_scratch[175243264];

// ===========================================================================
// helpers
// ===========================================================================
__device__ __forceinline__ uint32_t smem_u32(const void* p) {
    uint32_t a;
    asm("{ .reg .u64 t; cvta.to.shared.u64 t, %1; cvt.u32.u64 %0, t; }"
        : "=r"(a) : "l"(p));
    return a;
}
__device__ __forceinline__ uint32_t f2tf32(float x) {
    uint32_t r;
    asm("cvt.rna.tf32.f32 %0, %1;" : "=r"(r) : "f"(x));
    return r;
}
__device__ __forceinline__ void split_tf32(uint32_t xbits, uint32_t& hi, uint32_t& lo) {
    float x = __uint_as_float(xbits);
    hi = f2tf32(x);
    lo = f2tf32(x - __uint_as_float(hi));
}
__device__ __forceinline__ float sigmoidf_(float x) { return 1.f / (1.f + expf(-x)); }

__device__ __forceinline__ void cp16(uint32_t s, const void* g) {
    asm volatile("cp.async.cg.shared.global [%0], [%1], 16;" :: "r"(s), "l"(g));
}

// scalar bf16 hi/lo split store
__device__ __forceinline__ void bsplit_store(__nv_bfloat16* H, __nv_bfloat16* L,
                                             long i, float v) {
    __nv_bfloat16 h = __float2bfloat16(v);
    H[i] = h;
    L[i] = __float2bfloat16(v - __bfloat162float(h));
}
__device__ __forceinline__ void bpair_store(__nv_bfloat16* H, __nv_bfloat16* L,
                                            long idx, float vx, float vy) {
    __nv_bfloat16 hx = __float2bfloat16(vx);
    __nv_bfloat16 hy = __float2bfloat16(vy);
    __nv_bfloat16 lx = __float2bfloat16(vx - __bfloat162float(hx));
    __nv_bfloat16 ly = __float2bfloat16(vy - __bfloat162float(hy));
    __nv_bfloat162 hp; hp.x = hx; hp.y = hy;
    __nv_bfloat162 lp; lp.x = lx; lp.y = ly;
    *(__nv_bfloat162*)(H + idx) = hp;
    *(__nv_bfloat162*)(L + idx) = lp;
}

__device__ __forceinline__ void mma1688(float* c, const uint32_t* a, const uint32_t* b) {
    asm volatile(
        "mma.sync.aligned.m16n8k8.row.col.f32.tf32.tf32.f32 "
        "{%0,%1,%2,%3}, {%4,%5,%6,%7}, {%8,%9}, {%0,%1,%2,%3};"
        : "+f"(c[0]), "+f"(c[1]), "+f"(c[2]), "+f"(c[3])
        : "r"(a[0]), "r"(a[1]), "r"(a[2]), "r"(a[3]), "r"(b[0]), "r"(b[1]));
}
__device__ __forceinline__ void mma16816(float* c, const uint32_t* a, const uint32_t* b) {
    asm volatile(
        "mma.sync.aligned.m16n8k16.row.col.f32.bf16.bf16.f32 "
        "{%0,%1,%2,%3}, {%4,%5,%6,%7}, {%8,%9}, {%0,%1,%2,%3};"
        : "+f"(c[0]), "+f"(c[1]), "+f"(c[2]), "+f"(c[3])
        : "r"(a[0]), "r"(a[1]), "r"(a[2]), "r"(a[3]), "r"(b[0]), "r"(b[1]));
}
__device__ __forceinline__ void ldm_x4(uint32_t* r, uint32_t a) {
    asm volatile("ldmatrix.sync.aligned.m8n8.x4.shared.b16 {%0,%1,%2,%3}, [%4];"
        : "=r"(r[0]), "=r"(r[1]), "=r"(r[2]), "=r"(r[3]) : "r"(a));
}

// ===========================================================================
// bf16x3 GEMM (NT): C = (Ah+Al)(Bh+Bl)^T via al*bh + ah*bl + ah*bh
// BM=BN=128, BK=32 bf16, 3-stage cp.async, single-sync pipeline, 256 thr.
// MODE 0 supports a TRIPLE merged launch via blockIdx.z (sets 1/2/3).
// MODE 6: blockIdx.x<32 -> Kc (relu^2, bf16 pair), else -> R2 (fp32).
// ===========================================================================
#define BTILE 8192                    // 128*32*2
#define BSTG  (4 * BTILE)             // 32768
#define BNSTG 3
#define BF_DSMEM (BNSTG * BSTG + 128) // 98432

__device__ __forceinline__ void load_stage_bf(
    uint32_t sbase, int stage,
    const __nv_bfloat16* __restrict__ Ah, const __nv_bfloat16* __restrict__ Al,
    const __nv_bfloat16* __restrict__ Bh, const __nv_bfloat16* __restrict__ Bl,
    int bm, int bn, int k0, int K, int tid)
{
    uint32_t s = sbase + stage * BSTG;
#pragma unroll
    for (int j = 0; j < 2; j++) {
        int gi = tid + j * 256;        // 0..511
        int row = gi >> 2, g = gi & 3;
        uint32_t so = (uint32_t)(row * 64 + ((g ^ ((row >> 1) & 3)) << 4));
        long ao = (long)(bm + row) * K + k0 + g * 8;
        long bo = (long)(bn + row) * K + k0 + g * 8;
        cp16(s + so,             Ah + ao);
        cp16(s + BTILE + so,     Al + ao);
        cp16(s + 2 * BTILE + so, Bh + bo);
        cp16(s + 3 * BTILE + so, Bl + bo);
    }
}

template<int MODE>
__global__ void __launch_bounds__(256, 2) gemm_bf(
    const __nv_bfloat16* __restrict__ Ah, const __nv_bfloat16* __restrict__ Al,
    const __nv_bfloat16* __restrict__ Bh, const __nv_bfloat16* __restrict__ Bl,
    const float* __restrict__ bias1,
    const float* __restrict__ ex1, const float* __restrict__ ex2,
    float* __restrict__ Of,
    __nv_bfloat16* __restrict__ Oh, __nv_bfloat16* __restrict__ Ol,
    int M, int N, int K,
    const __nv_bfloat16* A2h, const __nv_bfloat16* A2l,
    const __nv_bfloat16* B2h, const __nv_bfloat16* B2l, float* Of2,
    const __nv_bfloat16* A3h, const __nv_bfloat16* A3l,
    const __nv_bfloat16* B3h, const __nv_bfloat16* B3l, float* Of3,
    const float* bias3)
{
    extern __shared__ __align__(16) char dsm[];

    bool second = false;   // MODE 6: R2 sub-launch
    int bn;
    if (MODE == 0) {
        if (blockIdx.z == 1) { Ah = A2h; Al = A2l; Bh = B2h; Bl = B2l; Of = Of2; }
        else if (blockIdx.z == 2) {
            Ah = A3h; Al = A3l; Bh = B3h; Bl = B3l; Of = Of3; bias1 = bias3;
        }
        bn = blockIdx.x * 128;
    } else if (MODE == 6) {
        if (blockIdx.x < 32) {
            bn = blockIdx.x * 128;            // Kc path, N stays 4096
        } else {
            second = true;
            Ah = A2h; Al = A2l; Bh = B2h; Bl = B2l;
            N = 1024;
            bn = (blockIdx.x - 32) * 128;     // R2 path
        }
    } else {
        bn = blockIdx.x * 128;
    }

    const int tid  = threadIdx.x;
    const int wid  = tid >> 5;
    const int lane = tid & 31;
    const int wm   = wid & 1;
    const int wn   = wid >> 1;
    const int bm = blockIdx.y * 128;
    const int KT = K / 32;
    const int lr = lane >> 2, lk = lane & 3;

    float acc[4][4][4];
#pragma unroll
    for (int i = 0; i < 4; i++)
#pragma unroll
        for (int j = 0; j < 4; j++)
#pragma unroll
            for (int r = 0; r < 4; r++) acc[i][j][r] = 0.f;

    // ldmatrix per-lane swizzled base offsets (granule bit from lane>>4)
    uint32_t offA[4], offB[2];
    {
        int ga = (lane >> 4) & 1;
        int rb = wm * 64 + (lane & 15);
#pragma unroll
        for (int mf = 0; mf < 4; mf++) {
            int row = rb + mf * 16;
            offA[mf] = (uint32_t)(row * 64 + ((ga ^ ((row >> 1) & 3)) << 4));
        }
#pragma unroll
        for (int pg = 0; pg < 2; pg++) {
            int row = wn * 32 + pg * 16 + (lane & 15);
            offB[pg] = (uint32_t)(row * 64 + ((ga ^ ((row >> 1) & 3)) << 4)) + 2 * BTILE;
        }
    }

    uint32_t sbase = (smem_u32(dsm) + 127u) & ~127u;
    load_stage_bf(sbase, 0, Ah, Al, Bh, Bl, bm, bn, 0, K, tid);
    asm volatile("cp.async.commit_group;" ::: "memory");
    load_stage_bf(sbase, 1, Ah, Al, Bh, Bl, bm, bn, 32, K, tid);
    asm volatile("cp.async.commit_group;" ::: "memory");

    int stage = 0;
    for (int kt = 0; kt < KT; kt++) {
        asm volatile("cp.async.wait_group 1;" ::: "memory");
        __syncthreads();   // also orders kt-1 MMAs before overwriting stage kt+2

        int ps = kt + 2;
        if (ps < KT) {
            int pstage = stage + 2; if (pstage >= BNSTG) pstage -= BNSTG;
            load_stage_bf(sbase, pstage, Ah, Al, Bh, Bl, bm, bn, ps * 32, K, tid);
        }
        asm volatile("cp.async.commit_group;" ::: "memory");

        uint32_t st = sbase + stage * BSTG;

#pragma unroll
        for (int ks = 0; ks < 2; ks++) {
            uint32_t kx = (uint32_t)(ks << 5);
            uint32_t tb0[4], tl0[4], tb1[4], tl1[4];
            ldm_x4(tb0, (st + offB[0]) ^ kx);
            ldm_x4(tl0, (st + offB[0] + BTILE) ^ kx);
            ldm_x4(tb1, (st + offB[1]) ^ kx);
            ldm_x4(tl1, (st + offB[1] + BTILE) ^ kx);
            uint32_t ah[4][4], al[4][4];
#pragma unroll
            for (int mf = 0; mf < 4; mf++) {
                ldm_x4(ah[mf], (st + offA[mf]) ^ kx);
                ldm_x4(al[mf], (st + offA[mf] + BTILE) ^ kx);
            }
            uint32_t b_h[4][2] = {{tb0[0],tb0[2]},{tb0[1],tb0[3]},
                                  {tb1[0],tb1[2]},{tb1[1],tb1[3]}};
            uint32_t b_l[4][2] = {{tl0[0],tl0[2]},{tl0[1],tl0[3]},
                                  {tl1[0],tl1[2]},{tl1[1],tl1[3]}};
#pragma unroll
            for (int mf = 0; mf < 4; mf++)
#pragma unroll
                for (int nf = 0; nf < 4; nf++)
                    mma16816(acc[mf][nf], al[mf], b_h[nf]);
#pragma unroll
            for (int mf = 0; mf < 4; mf++)
#pragma unroll
                for (int nf = 0; nf < 4; nf++)
                    mma16816(acc[mf][nf], ah[mf], b_l[nf]);
#pragma unroll
            for (int mf = 0; mf < 4; mf++)
#pragma unroll
                for (int nf = 0; nf < 4; nf++)
                    mma16816(acc[mf][nf], ah[mf], b_h[nf]);
        }
        stage++; if (stage >= BNSTG) stage = 0;
    }

    // epilogue
#pragma unroll
    for (int mf = 0; mf < 4; mf++) {
        int r0 = bm + wm * 64 + mf * 16 + lr;
#pragma unroll
        for (int nf = 0; nf < 4; nf++) {
            int c0 = bn + wn * 32 + nf * 8 + lk * 2;
#pragma unroll
            for (int h = 0; h < 2; h++) {
                int row = r0 + h * 8;
                long idx = (long)row * N + c0;
                float vx = acc[mf][nf][2 * h + 0];
                float vy = acc[mf][nf][2 * h + 1];
                if (MODE == 0) {
                    if (bias1) { vx += bias1[c0]; vy += bias1[c0 + 1]; }
                    *(float2*)(Of + idx) = make_float2(vx, vy);
                } else if (MODE == 1) {
                    vx = fmaxf(vx, 0.f); vx *= vx;
                    vy = fmaxf(vy, 0.f); vy *= vy;
                    bpair_store(Oh, Ol, idx, vx, vy);
                } else if (MODE == 3) {
                    vx += bias1[c0]; vy += bias1[c0 + 1];
                    float rx = sigmoidf_(ex1[idx])     * (vx + ex2[idx]);
                    float ry = sigmoidf_(ex1[idx + 1]) * (vy + ex2[idx + 1]);
                    bpair_store(Oh, Ol, idx, rx, ry);
                } else if (MODE == 4) {
                    *(float2*)(Of + idx) = make_float2(ex1[idx] + vx, ex1[idx + 1] + vy);
                } else if (MODE == 5) {
                    float rx = ex1[idx]     + sigmoidf_(ex2[idx])     * vx;
                    float ry = ex1[idx + 1] + sigmoidf_(ex2[idx + 1]) * vy;
                    *(float2*)(Of + idx) = make_float2(rx, ry);
                } else { // MODE 6
                    if (!second) {
                        vx = fmaxf(vx, 0.f); vx *= vx;
                        vy = fmaxf(vy, 0.f); vy *= vy;
                        bpair_store(Oh, Ol, idx, vx, vy);
                    } else {
                        *(float2*)(Of2 + idx) = make_float2(vx, vy);
                    }
                }
            }
        }
    }
}

// ===========================================================================
// tf32x3 GEMM (NT) with in-kernel split (fp32 inputs) — precision path.
// ===========================================================================
#define TBKF 16
#define T_A_BYTES (128 * TBKF * 4)      // 8192
#define T_STG     (2 * T_A_BYTES)       // 16384
#define TNSTG 4
#define TF_DSMEM (TNSTG * T_STG)        // 65536

__device__ __forceinline__ uint32_t lde(const uint32_t* t, int row, int k) {
    int g = k >> 2;
    return t[row * 16 + (((g ^ ((row >> 1) & 3)) << 2) | (k & 3))];
}

__device__ __forceinline__ void load_stage_tf(
    uint32_t sbase, int stage, const float* __restrict__ A,
    const float* __restrict__ B, int bm, int bn, int k0, int K, int tid)
{
    uint32_t sa = sbase + stage * T_STG;
    uint32_t sb = sa + T_A_BYTES;
    int row = tid >> 1;
    int g0 = (tid & 1) * 2;
#pragma unroll
    for (int j = 0; j < 2; j++) {
        int g = g0 + j;
        uint32_t so = (uint32_t)(row * 64 + ((g ^ ((row >> 1) & 3)) << 4));
        cp16(sa + so, A + (long)(bm + row) * K + k0 + g * 4);
        cp16(sb + so, B + (long)(bn + row) * K + k0 + g * 4);
    }
}

template<int MODE>
__global__ void __launch_bounds__(256) gemm_tf(
    const float* __restrict__ A, const float* __restrict__ B,
    const float* __restrict__ qb, const float* __restrict__ kb,
    float* __restrict__ O1, float* __restrict__ Qf, float* __restrict__ Kf,
    int M, int N, int K, float alpha, long sA, long sB, long sC)
{
    extern __shared__ __align__(16) char dsm[];

    A += (long)blockIdx.z * sA;
    B += (long)blockIdx.z * sB;
    O1 += (long)blockIdx.z * sC;

    const int tid  = threadIdx.x;
    const int wid  = tid >> 5;
    const int lane = tid & 31;
    const int wm   = wid & 1;
    const int wn   = wid >> 1;
    const int bm = blockIdx.y * 128;
    const int bn = blockIdx.x * 128;
    const int KT = K / TBKF;

    uint32_t sbase = smem_u32(dsm);

    float acc[4][4][4];
#pragma unroll
    for (int i = 0; i < 4; i++)
#pragma unroll
        for (int j = 0; j < 4; j++)
#pragma unroll
            for (int r = 0; r < 4; r++) acc[i][j][r] = 0.f;

#pragma unroll
    for (int s = 0; s < TNSTG - 1; s++) {
        if (s < KT) load_stage_tf(sbase, s, A, B, bm, bn, s * TBKF, K, tid);
        asm volatile("cp.async.commit_group;" ::: "memory");
    }

    const int lr = lane >> 2;
    const int lk = lane & 3;

    for (int kt = 0; kt < KT; kt++) {
        __syncthreads();
        if (kt + 3 < KT)
            load_stage_tf(sbase, (kt + 3) & 3, A, B, bm, bn, (kt + 3) * TBKF, K, tid);
        asm volatile("cp.async.commit_group;" ::: "memory");
        asm volatile("cp.async.wait_group 3;" ::: "memory");
        __syncthreads();

        const uint32_t* sa = (const uint32_t*)(dsm + (size_t)(kt & 3) * T_STG);
        const uint32_t* sb = sa + 128 * TBKF;

#pragma unroll
        for (int ks = 0; ks < 2; ks++) {
            int kbase = ks * 8;
            uint32_t ah[4][4], al[4][4], bh[4][2], bl[4][2];
#pragma unroll
            for (int mf = 0; mf < 4; mf++) {
                int r0 = wm * 64 + mf * 16 + lr;
                split_tf32(lde(sa, r0,     kbase + lk),     ah[mf][0], al[mf][0]);
                split_tf32(lde(sa, r0 + 8, kbase + lk),     ah[mf][1], al[mf][1]);
                split_tf32(lde(sa, r0,     kbase + lk + 4), ah[mf][2], al[mf][2]);
                split_tf32(lde(sa, r0 + 8, kbase + lk + 4), ah[mf][3], al[mf][3]);
            }
#pragma unroll
            for (int nf = 0; nf < 4; nf++) {
                int n0 = wn * 32 + nf * 8 + lr;
                split_tf32(lde(sb, n0, kbase + lk),     bh[nf][0], bl[nf][0]);
                split_tf32(lde(sb, n0, kbase + lk + 4), bh[nf][1], bl[nf][1]);
            }
#pragma unroll
            for (int mf = 0; mf < 4; mf++)
#pragma unroll
                for (int nf = 0; nf < 4; nf++)
                    mma1688(acc[mf][nf], al[mf], bh[nf]);
#pragma unroll
            for (int mf = 0; mf < 4; mf++)
#pragma unroll
                for (int nf = 0; nf < 4; nf++)
                    mma1688(acc[mf][nf], ah[mf], bl[nf]);
#pragma unroll
            for (int mf = 0; mf < 4; mf++)
#pragma unroll
                for (int nf = 0; nf < 4; nf++)
                    mma1688(acc[mf][nf], ah[mf], bh[nf]);
        }
    }

#pragma unroll
    for (int mf = 0; mf < 4; mf++) {
        int r0 = bm + wm * 64 + mf * 16 + lr;
#pragma unroll
        for (int nf = 0; nf < 4; nf++) {
            int c0 = bn + wn * 32 + nf * 8 + lk * 2;
#pragma unroll
            for (int h = 0; h < 2; h++) {
                int row = r0 + h * 8;
                float vx = acc[mf][nf][2 * h + 0] * alpha;
                float vy = acc[mf][nf][2 * h + 1] * alpha;
                if (MODE == 0) {
                    *(float2*)(O1 + (long)row * N + c0) = make_float2(vx, vy);
                } else { // MODE 2: Q||K
                    if (c0 < 64) {
                        vx += qb[c0]; vy += qb[c0 + 1];
                        *(float2*)(Qf + (long)row * 64 + c0) = make_float2(vx, vy);
                    } else {
                        vx += kb[c0 - 64]; vy += kb[c0 - 63];
                        *(float2*)(Kf + (long)row * 64 + c0 - 64) = make_float2(vx, vy);
                    }
                }
            }
        }
    }
}

// ---------------------------------------------------------------------------
// Weight splits: fp32 -> bf16 hi/lo, one fused launch (8 jobs, guarded)
// ---------------------------------------------------------------------------
struct SplitJob { const float* src; __nv_bfloat16* h; __nv_bfloat16* l; long n; };
struct SplitJobs8 { SplitJob j[8]; };

__global__ void __launch_bounds__(256) split8(SplitJobs8 jobs)
{
    const SplitJob jb = jobs.j[blockIdx.y];
    long i = ((long)blockIdx.x * 256 + threadIdx.x) * 2;
    if (i < jb.n) bpair_store(jb.h, jb.l, i, jb.src[i], jb.src[i + 1]);
}

__global__ void __launch_bounds__(256) concat_qk(
    const float* __restrict__ q, const float* __restrict__ k, float* __restrict__ o)
{
    int i = blockIdx.x * 256 + threadIdx.x;   // n = 131072
    o[i] = (i < 65536) ? q[i] : k[i - 65536];
}

// ---------------------------------------------------------------------------
// Fused RMSNorm + token-shift mixing.
// ---------------------------------------------------------------------------
template<int WRITE_H>
__global__ void __launch_bounds__(256) norm_mix_kernel(
    const float* __restrict__ x, const float* __restrict__ w,
    const float* __restrict__ mA, const float* __restrict__ mB,
    __nv_bfloat16* __restrict__ oAh, __nv_bfloat16* __restrict__ oAl,
    __nv_bfloat16* __restrict__ oBh, __nv_bfloat16* __restrict__ oBl,
    float* __restrict__ hF, __nv_bfloat16* __restrict__ hbH,
    __nv_bfloat16* __restrict__ hbL)
{
    long row = blockIdx.x;
    long prev = ((row & (S_LEN - 1)) == 0) ? row : row - 1;
    int tid = threadIdx.x;
    const float* xc = x + row * D_DIM;
    const float* xp = x + prev * D_DIM;

    float c[4], p[4];
    float sc_ = 0.f, sp_ = 0.f;
#pragma unroll
    for (int d = 0; d < 4; d++) {
        c[d] = xc[tid + d * 256];
        p[d] = xp[tid + d * 256];
        sc_ += c[d] * c[d];
        sp_ += p[d] * p[d];
    }
#pragma unroll
    for (int o = 16; o > 0; o >>= 1) {
        sc_ += __shfl_xor_sync(0xffffffffu, sc_, o);
        sp_ += __shfl_xor_sync(0xffffffffu, sp_, o);
    }

    __shared__ float redc[8], redp[8];
    __shared__ float s_invc, s_invp;
    if ((tid & 31) == 0) { redc[tid >> 5] = sc_; redp[tid >> 5] = sp_; }
    __syncthreads();
    if (tid == 0) {
        float tc = 0.f, tp = 0.f;
#pragma unroll
        for (int i = 0; i < 8; i++) { tc += redc[i]; tp += redp[i]; }
        s_invc = 1.0f / (sqrtf(tc / (float)D_DIM) + 1e-8f);
        s_invp = 1.0f / (sqrtf(tp / (float)D_DIM) + 1e-8f);
    }
    __syncthreads();
    float invc = s_invc, invp = s_invp;

#pragma unroll
    for (int d = 0; d < 4; d++) {
        int cc = tid + d * 256;
        long ci = row * D_DIM + cc;
        float nc = w[cc] * c[d] * invc;
        float np = w[cc] * p[d] * invp;
        float a = mA[cc], b = mB[cc];
        bsplit_store(oAh, oAl, ci, nc * a + np * (1.f - a));
        bsplit_store(oBh, oBl, ci, nc * b + np * (1.f - b));
        if (WRITE_H) {
            hF[ci] = nc;
            bsplit_store(hbH, hbL, ci, nc);
        }
    }
}

// ---------------------------------------------------------------------------
// Sparse attention: chunked top-32, softmax, attn@V -> bf16 pair out.
// ---------------------------------------------------------------------------
__global__ void __launch_bounds__(256) sparse_attn_kernel(
    const float* __restrict__ scores, const float* __restrict__ V,
    __nv_bfloat16* __restrict__ oh, __nv_bfloat16* __restrict__ ol)
{
    __shared__ float sc[S_LEN];
    __shared__ float cmax[128];
    __shared__ float selV[TOPK];
    __shared__ int   selI[TOPK];
    __shared__ float wsel[TOPK];

    long row = blockIdx.x;
    long b = row >> 12;
    int tid = threadIdx.x;
    int lane = tid & 31;

    const float* srow = scores + row * S_LEN;
    for (int i = tid; i < S_LEN; i += 256) sc[i] = srow[i];
    __syncthreads();

    if (tid < 128) {
        float m = NEG_INF;
#pragma unroll 8
        for (int i = 0; i < 32; i++) m = fmaxf(m, sc[tid * 32 + i]);
        cmax[tid] = m;
    }
    __syncthreads();

    if (tid < 32) {
        for (int it = 0; it < TOPK; it++) {
            float bv = NEG_INF; int bc = 0;
#pragma unroll
            for (int j = 0; j < 4; j++) {
                int c = lane * 4 + j;
                float v = cmax[c];
                if (v > bv) { bv = v; bc = c; }
            }
#pragma unroll
            for (int o = 16; o > 0; o >>= 1) {
                float ov = __shfl_down_sync(0xffffffffu, bv, o);
                int   oc = __shfl_down_sync(0xffffffffu, bc, o);
                if (ov > bv || (ov == bv && oc < bc)) { bv = ov; bc = oc; }
            }
            bc = __shfl_sync(0xffffffffu, bc, 0);

            float v = sc[bc * 32 + lane];
            float mv = v; int mi = lane;
#pragma unroll
            for (int o = 16; o > 0; o >>= 1) {
                float ov = __shfl_down_sync(0xffffffffu, mv, o);
                int   oi = __shfl_down_sync(0xffffffffu, mi, o);
                if (ov > mv || (ov == mv && oi < mi)) { mv = ov; mi = oi; }
            }
            mv = __shfl_sync(0xffffffffu, mv, 0);
            mi = __shfl_sync(0xffffffffu, mi, 0);

            if (lane == mi) { sc[bc * 32 + lane] = NEG_INF; v = NEG_INF; }
            if (lane == 0) { selV[it] = mv; selI[it] = bc * 32 + mi; }

            float nm = v;
#pragma unroll
            for (int o = 16; o > 0; o >>= 1)
                nm = fmaxf(nm, __shfl_down_sync(0xffffffffu, nm, o));
            if (lane == 0) cmax[bc] = nm;
        }
        float m = __shfl_sync(0xffffffffu, selV[0], 0);
        float e = expf(selV[lane] - m);
        float s = e;
#pragma unroll
        for (int o = 16; o > 0; o >>= 1) s += __shfl_xor_sync(0xffffffffu, s, o);
        wsel[lane] = e / s;
    }
    __syncthreads();

    float acc[4] = {0.f, 0.f, 0.f, 0.f};
    const float* Vb = V + b * (long)S_LEN * D_DIM;
#pragma unroll 1
    for (int j = 0; j < TOPK; j++) {
        float w = wsel[j];
        const float* vr = Vb + (long)selI[j] * D_DIM;
#pragma unroll
        for (int d = 0; d < 4; d++) acc[d] += w * vr[tid + d * 256];
    }
#pragma unroll
    for (int d = 0; d < 4; d++)
        bsplit_store(oh, ol, row * D_DIM + tid + d * 256, acc[d]);
}

// ---------------------------------------------------------------------------
// Host launchers
// ---------------------------------------------------------------------------
typedef __nv_bfloat16 bf16;

static void launch_bf(cudaStream_t st, int mode,
    const bf16* Ah, const bf16* Al, const bf16* Bh, const bf16* Bl,
    const float* b1, const float* e1, const float* e2,
    float* Of, bf16* Oh, bf16* Ol, int M, int N, int K,
    const bf16* A2h = nullptr, const bf16* A2l = nullptr,
    const bf16* B2h = nullptr, const bf16* B2l = nullptr, float* Of2 = nullptr,
    const bf16* A3h = nullptr, const bf16* A3l = nullptr,
    const bf16* B3h = nullptr, const bf16* B3l = nullptr, float* Of3 = nullptr,
    const float* b3 = nullptr, int gx = -1, int gz = 1)
{
    dim3 grid(gx < 0 ? N / 128 : gx, M / 128, gz);
    switch (mode) {
    case 0: gemm_bf<0><<<grid, 256, BF_DSMEM, st>>>(Ah,Al,Bh,Bl,b1,e1,e2,Of,Oh,Ol,M,N,K,A2h,A2l,B2h,B2l,Of2,A3h,A3l,B3h,B3l,Of3,b3); break;
    case 1: gemm_bf<1><<<grid, 256, BF_DSMEM, st>>>(Ah,Al,Bh,Bl,b1,e1,e2,Of,Oh,Ol,M,N,K,A2h,A2l,B2h,B2l,Of2,A3h,A3l,B3h,B3l,Of3,b3); break;
    case 3: gemm_bf<3><<<grid, 256, BF_DSMEM, st>>>(Ah,Al,Bh,Bl,b1,e1,e2,Of,Oh,Ol,M,N,K,A2h,A2l,B2h,B2l,Of2,A3h,A3l,B3h,B3l,Of3,b3); break;
    case 4: gemm_bf<4><<<grid, 256, BF_DSMEM, st>>>(Ah,Al,Bh,Bl,b1,e1,e2,Of,Oh,Ol,M,N,K,A2h,A2l,B2h,B2l,Of2,A3h,A3l,B3h,B3l,Of3,b3); break;
    case 5: gemm_bf<5><<<grid, 256, BF_DSMEM, st>>>(Ah,Al,Bh,Bl,b1,e1,e2,Of,Oh,Ol,M,N,K,A2h,A2l,B2h,B2l,Of2,A3h,A3l,B3h,B3l,Of3,b3); break;
    default: gemm_bf<6><<<grid, 256, BF_DSMEM, st>>>(Ah,Al,Bh,Bl,b1,e1,e2,Of,Oh,Ol,M,N,K,A2h,A2l,B2h,B2l,Of2,A3h,A3l,B3h,B3l,Of3,b3); break;
    }
}

extern "C" void kernel_launch(void* const* d_in, const int* in_sizes, int n_in,
                              void* d_out, int out_size)
{
    const float* x         = (const float*)d_in[0];
    const float* norm1_w   = (const float*)d_in[1];
    const float* tm_mix_v  = (const float*)d_in[3];
    const float* tm_mix_r  = (const float*)d_in[4];
    const float* tm_value_w  = (const float*)d_in[6];
    const float* tm_recept_w = (const float*)d_in[7];
    const float* tm_out_w    = (const float*)d_in[8];
    const float* sa_q_w    = (const float*)d_in[9];
    const float* sa_q_b    = (const float*)d_in[10];
    const float* sa_k_w    = (const float*)d_in[11];
    const float* sa_k_b    = (const float*)d_in[12];
    const float* sa_v_w    = (const float*)d_in[13];
    const float* sa_v_b    = (const float*)d_in[14];
    const float* sa_o_w    = (const float*)d_in[15];
    const float* sa_o_b    = (const float*)d_in[16];
    const float* norm2_w   = (const float*)d_in[17];
    const float* cm_mix_k  = (const float*)d_in[18];
    const float* cm_mix_r  = (const float*)d_in[19];
    const float* cm_key_w    = (const float*)d_in[20];
    const float* cm_recept_w = (const float*)d_in[21];
    const float* cm_value_w  = (const float*)d_in[22];
    float* out = (float*)d_out;

    cudaFuncSetAttribute(gemm_bf<0>, cudaFuncAttributeMaxDynamicSharedMemorySize, BF_DSMEM);
    cudaFuncSetAttribute(gemm_bf<1>, cudaFuncAttributeMaxDynamicSharedMemorySize, BF_DSMEM);
    cudaFuncSetAttribute(gemm_bf<3>, cudaFuncAttributeMaxDynamicSharedMemorySize, BF_DSMEM);
    cudaFuncSetAttribute(gemm_bf<4>, cudaFuncAttributeMaxDynamicSharedMemorySize, BF_DSMEM);
    cudaFuncSetAttribute(gemm_bf<5>, cudaFuncAttributeMaxDynamicSharedMemorySize, BF_DSMEM);
    cudaFuncSetAttribute(gemm_bf<6>, cudaFuncAttributeMaxDynamicSharedMemorySize, BF_DSMEM);
    cudaFuncSetAttribute(gemm_tf<0>, cudaFuncAttributeMaxDynamicSharedMemorySize, TF_DSMEM);
    cudaFuncSetAttribute(gemm_tf<2>, cudaFuncAttributeMaxDynamicSharedMemorySize, TF_DSMEM);

    float* sp = nullptr;
    cudaGetSymbolAddress((void**)&sp, g_scratch);

    float* hF   = sp + O_HF;
    float* Vtm  = sp + O_VTM;
    float* Rtm  = sp + O_RTM;
    float* Vv   = sp + O_VV;
    float* x2   = sp + O_X2;
    float* R2   = sp + O_R2;
    float* Qf   = sp + O_Q;
    float* Kf   = sp + O_K;
    float* wQKf = sp + O_WQKF;
    float* SCo  = sp + O_SC;

    bf16* hbH = (bf16*)(sp + O_BHB); bf16* hbL = (bf16*)(sp + O_BHL);
    bf16* xvH = (bf16*)(sp + O_XVH); bf16* xvL = (bf16*)(sp + O_XVL);
    bf16* xrH = (bf16*)(sp + O_XRH); bf16* xrL = (bf16*)(sp + O_XRL);
    bf16* atH = (bf16*)(sp + O_ATH); bf16* atL = (bf16*)(sp + O_ATL);
    bf16* rkH = (bf16*)(sp + O_RKH); bf16* rkL = (bf16*)(sp + O_RKL);
    bf16* KcH = (bf16*)(sp + O_KCH); bf16* KcL = (bf16*)(sp + O_KCL);

    bf16* wTMVh = (bf16*)(sp + O_WTMV); bf16* wTMVl = wTMVh + 1048576L;
    bf16* wTMRh = (bf16*)(sp + O_WTMR); bf16* wTMRl = wTMRh + 1048576L;
    bf16* wSAVh = (bf16*)(sp + O_WSAV); bf16* wSAVl = wSAVh + 1048576L;
    bf16* wSAOh = (bf16*)(sp + O_WSAO); bf16* wSAOl = wSAOh + 1048576L;
    bf16* wTMOh = (bf16*)(sp + O_WTMO); bf16* wTMOl = wTMOh + 1048576L;
    bf16* wCMRh = (bf16*)(sp + O_WCMR); bf16* wCMRl = wCMRh + 1048576L;
    bf16* wCMKh = (bf16*)(sp + O_WCMK); bf16* wCMKl = wCMKh + 4194304L;
    bf16* wCMVh = (bf16*)(sp + O_WCMV); bf16* wCMVl = wCMVh + 4194304L;

    // side stream + fork/join events (created per call; host-side only)
    cudaStream_t s1;
    cudaStreamCreateWithFlags(&s1, cudaStreamNonBlocking);
    cudaEvent_t eRoot, eSplit, eNM, eSc;
    cudaEventCreateWithFlags(&eRoot,  cudaEventDisableTiming);
    cudaEventCreateWithFlags(&eSplit, cudaEventDisableTiming);
    cudaEventCreateWithFlags(&eNM,    cudaEventDisableTiming);
    cudaEventCreateWithFlags(&eSc,    cudaEventDisableTiming);

    // fork s1 from main stream
    cudaEventRecord(eRoot, 0);
    cudaStreamWaitEvent(s1, eRoot, 0);

    // s1: weight splits + QK weight concat
    {
        SplitJobs8 s8;
        s8.j[0] = {tm_value_w,  wTMVh, wTMVl, 1048576L};
        s8.j[1] = {tm_recept_w, wTMRh, wTMRl, 1048576L};
        s8.j[2] = {sa_v_w,      wSAVh, wSAVl, 1048576L};
        s8.j[3] = {sa_o_w,      wSAOh, wSAOl, 1048576L};
        s8.j[4] = {tm_out_w,    wTMOh, wTMOl, 1048576L};
        s8.j[5] = {cm_recept_w, wCMRh, wCMRl, 1048576L};
        s8.j[6] = {cm_key_w,    wCMKh, wCMKl, 4194304L};
        s8.j[7] = {cm_value_w,  wCMVh, wCMVl, 4194304L};
        split8<<<dim3(8192, 8, 1), 256, 0, s1>>>(s8);
        concat_qk<<<512, 256, 0, s1>>>(sa_q_w, sa_k_w, wQKf);
        cudaEventRecord(eSplit, s1);
    }

    // main: norm_mix1 (independent of splits)
    norm_mix_kernel<1><<<NROWS, 256, 0, 0>>>(x, norm1_w, tm_mix_v, tm_mix_r,
                                             xvH, xvL, xrH, xrL, hF, hbH, hbL);
    cudaEventRecord(eNM, 0);

    // s1: QK projection (needs hF + wQKf) then scores — runs concurrent
    // with the main-stream triple GEMM below.
    cudaStreamWaitEvent(s1, eNM, 0);
    {
        dim3 g(1, NROWS / 128, 1);
        gemm_tf<2><<<g, 256, TF_DSMEM, s1>>>(hF, wQKf, sa_q_b, sa_k_b,
                                             nullptr, Qf, Kf, NROWS, 128, D_DIM,
                                             1.f, 0, 0, 0);
    }
    {
        dim3 g(S_LEN / 128, S_LEN / 128, B_SZ);
        gemm_tf<0><<<g, 256, TF_DSMEM, s1>>>(Qf, Kf, nullptr, nullptr,
                                             SCo, nullptr, nullptr, S_LEN, S_LEN, A_DIM,
                                             0.125f, (long)S_LEN * A_DIM,
                                             (long)S_LEN * A_DIM, (long)S_LEN * S_LEN);
    }
    cudaEventRecord(eSc, s1);

    // main: triple merged GEMM (needs weight splits)
    cudaStreamWaitEvent(0, eSplit, 0);
    launch_bf(0, 0, xvH, xvL, wTMVh, wTMVl, nullptr, nullptr, nullptr,
              Vtm, nullptr, nullptr, NROWS, D_DIM, D_DIM,
              xrH, xrL, wTMRh, wTMRl, Rtm,
              hbH, hbL, wSAVh, wSAVl, Vv, sa_v_b, -1, 3);

    // main: join scores chain, then sparse attention (needs SCo + Vv)
    cudaStreamWaitEvent(0, eSc, 0);
    sparse_attn_kernel<<<NROWS, 256, 0, 0>>>(SCo, Vv, atH, atL);

    // rkv = sigmoid(Rtm) * (attn@W_o + b_o + Vtm) -> bf16 pair
    launch_bf(0, 3, atH, atL, wSAOh, wSAOl, sa_o_b, Rtm, Vtm,
              nullptr, rkH, rkL, NROWS, D_DIM, D_DIM);

    // x2 = x + rkv @ W_out
    launch_bf(0, 4, rkH, rkL, wTMOh, wTMOl, nullptr, x, nullptr,
              x2, nullptr, nullptr, NROWS, D_DIM, D_DIM);

    // --- channel-mix branch ---
    norm_mix_kernel<0><<<NROWS, 256, 0, 0>>>(x2, norm2_w, cm_mix_k, cm_mix_r,
                                             xvH, xvL, xrH, xrL,
                                             nullptr, nullptr, nullptr);

    // merged: blocks x<32 -> Kc = relu(xk2@W_k)^2 (bf16 pair), x>=32 -> R2
    launch_bf(0, 6, xvH, xvL, wCMKh, wCMKl, nullptr, nullptr, nullptr,
              nullptr, KcH, KcL, NROWS, DI_DIM, D_DIM,
              xrH, xrL, wCMRh, wCMRl, R2,
              nullptr, nullptr, nullptr, nullptr, nullptr, nullptr, 40, 1);

    // out = x2 + sigmoid(R2) * (Kc @ W_v)
    launch_bf(0, 5, KcH, KcL, wCMVh, wCMVl, nullptr, x2, R2,
              out, nullptr, nullptr, NROWS, D_DIM, DI_DIM);

    cudaEventDestroy(eRoot);
    cudaEventDestroy(eSplit);
    cudaEventDestroy(eNM);
    cudaEventDestroy(eSc);
    cudaStreamDestroy(s1);
}

// round 17
// speedup vs baseline: 1.0333x; 1.0244x over previous
#include <cuda_runtime.h>
#include <cuda_bf16.h>
#include <math.h>
#include <stdint.h>

// Problem constants
#define D_DIM   1024
#define S_LEN   4096
#define B_SZ    2
#define A_DIM   64
#define DI_DIM  4096
#define TOPK    32
#define NROWS   (B_SZ * S_LEN)                 // 8192
#define ROWELEMS ((long)NROWS * D_DIM)         // 8,388,608

#define NEG_INF (-3.402823466e38f)

// ---------------------------------------------------------------------------
// Scratch layout (float offsets; bf16 arrays overlay pairs of floats)
// ---------------------------------------------------------------------------
static const long O_HF   = 0L;
static const long O_VTM  = 8388608L;
static const long O_RTM  = 16777216L;
static const long O_VV   = 25165824L;
static const long O_X2   = 33554432L;
static const long O_R2   = 41943040L;
static const long O_Q    = 50331648L;   // 524288 fp32
static const long O_K    = 50855936L;   // 524288 fp32
static const long O_WQKF = 51380224L;   // 131072 fp32 (concat q/k weights)
static const long O_SC   = 51511296L;   // 33554432 fp32
// bf16 arrays (float-offset; each float slot holds 2 bf16)
static const long O_BHB = 85065728L;
static const long O_BHL = 89260032L;
static const long O_XVH = 93454336L;
static const long O_XVL = 97648640L;
static const long O_XRH = 101842944L;
static const long O_XRL = 106037248L;
static const long O_ATH = 110231552L;
static const long O_ATL = 114425856L;
static const long O_RKH = 118620160L;
static const long O_RKL = 122814464L;
static const long O_KCH = 127008768L;
static const long O_KCL = 143785984L;
static const long O_WB  = 160563200L;
static const long O_WTMV = O_WB;
static const long O_WTMR = O_WTMV + 1048576L;
static const long O_WSAV = O_WTMR + 1048576L;
static const long O_WSAO = O_WSAV + 1048576L;
static const long O_WTMO = O_WSAO + 1048576L;
static const long O_WCMR = O_WTMO + 1048576L;
static const long O_WCMK = O_WCMR + 1048576L;
static const long O_WCMV = O_WCMK + 4194304L;
static const long O_QKP  = O_WCMV + 4194304L;   // 4 x 8192 x 128 fp32 partials
// end = O_QKP + 4194304 = 179437568

__device__ __align__(16) float g_scratch[179437568];

// ===========================================================================
// helpers
// ===========================================================================
__device__ __forceinline__ uint32_t smem_u32(const void* p) {
    uint32_t a;
    asm("{ .reg .u64 t; cvta.to.shared.u64 t, %1; cvt.u32.u64 %0, t; }"
        : "=r"(a) : "l"(p));
    return a;
}
__device__ __forceinline__ uint32_t f2tf32(float x) {
    uint32_t r;
    asm("cvt.rna.tf32.f32 %0, %1;" : "=r"(r) : "f"(x));
    return r;
}
__device__ __forceinline__ void split_tf32(uint32_t xbits, uint32_t& hi, uint32_t& lo) {
    float x = __uint_as_float(xbits);
    hi = f2tf32(x);
    lo = f2tf32(x - __uint_as_float(hi));
}
__device__ __forceinline__ float sigmoidf_(float x) { return 1.f / (1.f + expf(-x)); }

__device__ __forceinline__ void cp16(uint32_t s, const void* g) {
    asm volatile("cp.async.cg.shared.global [%0], [%1], 16;" :: "r"(s), "l"(g));
}

// scalar bf16 hi/lo split store
__device__ __forceinline__ void bsplit_store(__nv_bfloat16* H, __nv_bfloat16* L,
                                             long i, float v) {
    __nv_bfloat16 h = __float2bfloat16(v);
    H[i] = h;
    L[i] = __float2bfloat16(v - __bfloat162float(h));
}
__device__ __forceinline__ void bpair_store(__nv_bfloat16* H, __nv_bfloat16* L,
                                            long idx, float vx, float vy) {
    __nv_bfloat16 hx = __float2bfloat16(vx);
    __nv_bfloat16 hy = __float2bfloat16(vy);
    __nv_bfloat16 lx = __float2bfloat16(vx - __bfloat162float(hx));
    __nv_bfloat16 ly = __float2bfloat16(vy - __bfloat162float(hy));
    __nv_bfloat162 hp; hp.x = hx; hp.y = hy;
    __nv_bfloat162 lp; lp.x = lx; lp.y = ly;
    *(__nv_bfloat162*)(H + idx) = hp;
    *(__nv_bfloat162*)(L + idx) = lp;
}

__device__ __forceinline__ void mma1688(float* c, const uint32_t* a, const uint32_t* b) {
    asm volatile(
        "mma.sync.aligned.m16n8k8.row.col.f32.tf32.tf32.f32 "
        "{%0,%1,%2,%3}, {%4,%5,%6,%7}, {%8,%9}, {%0,%1,%2,%3};"
        : "+f"(c[0]), "+f"(c[1]), "+f"(c[2]), "+f"(c[3])
        : "r"(a[0]), "r"(a[1]), "r"(a[2]), "r"(a[3]), "r"(b[0]), "r"(b[1]));
}
__device__ __forceinline__ void mma16816(float* c, const uint32_t* a, const uint32_t* b) {
    asm volatile(
        "mma.sync.aligned.m16n8k16.row.col.f32.bf16.bf16.f32 "
        "{%0,%1,%2,%3}, {%4,%5,%6,%7}, {%8,%9}, {%0,%1,%2,%3};"
        : "+f"(c[0]), "+f"(c[1]), "+f"(c[2]), "+f"(c[3])
        : "r"(a[0]), "r"(a[1]), "r"(a[2]), "r"(a[3]), "r"(b[0]), "r"(b[1]));
}
__device__ __forceinline__ void ldm_x4(uint32_t* r, uint32_t a) {
    asm volatile("ldmatrix.sync.aligned.m8n8.x4.shared.b16 {%0,%1,%2,%3}, [%4];"
        : "=r"(r[0]), "=r"(r[1]), "=r"(r[2]), "=r"(r[3]) : "r"(a));
}

// ===========================================================================
// bf16x3 GEMM (NT): C = (Ah+Al)(Bh+Bl)^T via al*bh + ah*bl + ah*bh
// BM=BN=128, BK=32 bf16, 3-stage cp.async, single-sync pipeline, 256 thr.
// MODE 0 supports a TRIPLE merged launch via blockIdx.z (sets 1/2/3).
// MODE 6: blockIdx.x<32 -> Kc (relu^2, bf16 pair), else -> R2 (fp32).
// ===========================================================================
#define BTILE 8192                    // 128*32*2
#define BSTG  (4 * BTILE)             // 32768
#define BNSTG 3
#define BF_DSMEM (BNSTG * BSTG + 128) // 98432

__device__ __forceinline__ void load_stage_bf(
    uint32_t sbase, int stage,
    const __nv_bfloat16* __restrict__ Ah, const __nv_bfloat16* __restrict__ Al,
    const __nv_bfloat16* __restrict__ Bh, const __nv_bfloat16* __restrict__ Bl,
    int bm, int bn, int k0, int K, int tid)
{
    uint32_t s = sbase + stage * BSTG;
#pragma unroll
    for (int j = 0; j < 2; j++) {
        int gi = tid + j * 256;        // 0..511
        int row = gi >> 2, g = gi & 3;
        uint32_t so = (uint32_t)(row * 64 + ((g ^ ((row >> 1) & 3)) << 4));
        long ao = (long)(bm + row) * K + k0 + g * 8;
        long bo = (long)(bn + row) * K + k0 + g * 8;
        cp16(s + so,             Ah + ao);
        cp16(s + BTILE + so,     Al + ao);
        cp16(s + 2 * BTILE + so, Bh + bo);
        cp16(s + 3 * BTILE + so, Bl + bo);
    }
}

template<int MODE>
__global__ void __launch_bounds__(256, 2) gemm_bf(
    const __nv_bfloat16* __restrict__ Ah, const __nv_bfloat16* __restrict__ Al,
    const __nv_bfloat16* __restrict__ Bh, const __nv_bfloat16* __restrict__ Bl,
    const float* __restrict__ bias1,
    const float* __restrict__ ex1, const float* __restrict__ ex2,
    float* __restrict__ Of,
    __nv_bfloat16* __restrict__ Oh, __nv_bfloat16* __restrict__ Ol,
    int M, int N, int K,
    const __nv_bfloat16* A2h, const __nv_bfloat16* A2l,
    const __nv_bfloat16* B2h, const __nv_bfloat16* B2l, float* Of2,
    const __nv_bfloat16* A3h, const __nv_bfloat16* A3l,
    const __nv_bfloat16* B3h, const __nv_bfloat16* B3l, float* Of3,
    const float* bias3)
{
    extern __shared__ __align__(16) char dsm[];

    bool second = false;   // MODE 6: R2 sub-launch
    int bn;
    if (MODE == 0) {
        if (blockIdx.z == 1) { Ah = A2h; Al = A2l; Bh = B2h; Bl = B2l; Of = Of2; }
        else if (blockIdx.z == 2) {
            Ah = A3h; Al = A3l; Bh = B3h; Bl = B3l; Of = Of3; bias1 = bias3;
        }
        bn = blockIdx.x * 128;
    } else if (MODE == 6) {
        if (blockIdx.x < 32) {
            bn = blockIdx.x * 128;            // Kc path, N stays 4096
        } else {
            second = true;
            Ah = A2h; Al = A2l; Bh = B2h; Bl = B2l;
            N = 1024;
            bn = (blockIdx.x - 32) * 128;     // R2 path
        }
    } else {
        bn = blockIdx.x * 128;
    }

    const int tid  = threadIdx.x;
    const int wid  = tid >> 5;
    const int lane = tid & 31;
    const int wm   = wid & 1;
    const int wn   = wid >> 1;
    const int bm = blockIdx.y * 128;
    const int KT = K / 32;
    const int lr = lane >> 2, lk = lane & 3;

    float acc[4][4][4];
#pragma unroll
    for (int i = 0; i < 4; i++)
#pragma unroll
        for (int j = 0; j < 4; j++)
#pragma unroll
            for (int r = 0; r < 4; r++) acc[i][j][r] = 0.f;

    // ldmatrix per-lane swizzled base offsets (granule bit from lane>>4)
    uint32_t offA[4], offB[2];
    {
        int ga = (lane >> 4) & 1;
        int rb = wm * 64 + (lane & 15);
#pragma unroll
        for (int mf = 0; mf < 4; mf++) {
            int row = rb + mf * 16;
            offA[mf] = (uint32_t)(row * 64 + ((ga ^ ((row >> 1) & 3)) << 4));
        }
#pragma unroll
        for (int pg = 0; pg < 2; pg++) {
            int row = wn * 32 + pg * 16 + (lane & 15);
            offB[pg] = (uint32_t)(row * 64 + ((ga ^ ((row >> 1) & 3)) << 4)) + 2 * BTILE;
        }
    }

    uint32_t sbase = (smem_u32(dsm) + 127u) & ~127u;
    load_stage_bf(sbase, 0, Ah, Al, Bh, Bl, bm, bn, 0, K, tid);
    asm volatile("cp.async.commit_group;" ::: "memory");
    load_stage_bf(sbase, 1, Ah, Al, Bh, Bl, bm, bn, 32, K, tid);
    asm volatile("cp.async.commit_group;" ::: "memory");

    int stage = 0;
    for (int kt = 0; kt < KT; kt++) {
        asm volatile("cp.async.wait_group 1;" ::: "memory");
        __syncthreads();   // also orders kt-1 MMAs before overwriting stage kt+2

        int ps = kt + 2;
        if (ps < KT) {
            int pstage = stage + 2; if (pstage >= BNSTG) pstage -= BNSTG;
            load_stage_bf(sbase, pstage, Ah, Al, Bh, Bl, bm, bn, ps * 32, K, tid);
        }
        asm volatile("cp.async.commit_group;" ::: "memory");

        uint32_t st = sbase + stage * BSTG;

#pragma unroll
        for (int ks = 0; ks < 2; ks++) {
            uint32_t kx = (uint32_t)(ks << 5);
            uint32_t tb0[4], tl0[4], tb1[4], tl1[4];
            ldm_x4(tb0, (st + offB[0]) ^ kx);
            ldm_x4(tl0, (st + offB[0] + BTILE) ^ kx);
            ldm_x4(tb1, (st + offB[1]) ^ kx);
            ldm_x4(tl1, (st + offB[1] + BTILE) ^ kx);
            uint32_t ah[4][4], al[4][4];
#pragma unroll
            for (int mf = 0; mf < 4; mf++) {
                ldm_x4(ah[mf], (st + offA[mf]) ^ kx);
                ldm_x4(al[mf], (st + offA[mf] + BTILE) ^ kx);
            }
            uint32_t b_h[4][2] = {{tb0[0],tb0[2]},{tb0[1],tb0[3]},
                                  {tb1[0],tb1[2]},{tb1[1],tb1[3]}};
            uint32_t b_l[4][2] = {{tl0[0],tl0[2]},{tl0[1],tl0[3]},
                                  {tl1[0],tl1[2]},{tl1[1],tl1[3]}};
#pragma unroll
            for (int mf = 0; mf < 4; mf++)
#pragma unroll
                for (int nf = 0; nf < 4; nf++)
                    mma16816(acc[mf][nf], al[mf], b_h[nf]);
#pragma unroll
            for (int mf = 0; mf < 4; mf++)
#pragma unroll
                for (int nf = 0; nf < 4; nf++)
                    mma16816(acc[mf][nf], ah[mf], b_l[nf]);
#pragma unroll
            for (int mf = 0; mf < 4; mf++)
#pragma unroll
                for (int nf = 0; nf < 4; nf++)
                    mma16816(acc[mf][nf], ah[mf], b_h[nf]);
        }
        stage++; if (stage >= BNSTG) stage = 0;
    }

    // epilogue
#pragma unroll
    for (int mf = 0; mf < 4; mf++) {
        int r0 = bm + wm * 64 + mf * 16 + lr;
#pragma unroll
        for (int nf = 0; nf < 4; nf++) {
            int c0 = bn + wn * 32 + nf * 8 + lk * 2;
#pragma unroll
            for (int h = 0; h < 2; h++) {
                int row = r0 + h * 8;
                long idx = (long)row * N + c0;
                float vx = acc[mf][nf][2 * h + 0];
                float vy = acc[mf][nf][2 * h + 1];
                if (MODE == 0) {
                    if (bias1) { vx += bias1[c0]; vy += bias1[c0 + 1]; }
                    *(float2*)(Of + idx) = make_float2(vx, vy);
                } else if (MODE == 1) {
                    vx = fmaxf(vx, 0.f); vx *= vx;
                    vy = fmaxf(vy, 0.f); vy *= vy;
                    bpair_store(Oh, Ol, idx, vx, vy);
                } else if (MODE == 3) {
                    vx += bias1[c0]; vy += bias1[c0 + 1];
                    float rx = sigmoidf_(ex1[idx])     * (vx + ex2[idx]);
                    float ry = sigmoidf_(ex1[idx + 1]) * (vy + ex2[idx + 1]);
                    bpair_store(Oh, Ol, idx, rx, ry);
                } else if (MODE == 4) {
                    *(float2*)(Of + idx) = make_float2(ex1[idx] + vx, ex1[idx + 1] + vy);
                } else if (MODE == 5) {
                    float rx = ex1[idx]     + sigmoidf_(ex2[idx])     * vx;
                    float ry = ex1[idx + 1] + sigmoidf_(ex2[idx + 1]) * vy;
                    *(float2*)(Of + idx) = make_float2(rx, ry);
                } else { // MODE 6
                    if (!second) {
                        vx = fmaxf(vx, 0.f); vx *= vx;
                        vy = fmaxf(vy, 0.f); vy *= vy;
                        bpair_store(Oh, Ol, idx, vx, vy);
                    } else {
                        *(float2*)(Of2 + idx) = make_float2(vx, vy);
                    }
                }
            }
        }
    }
}

// ===========================================================================
// tf32x3 GEMM (NT) with in-kernel split (fp32 inputs) — precision path.
// MODE 0: O1 = alpha*acc (batched via blockIdx.z strides)
// MODE 4: QK split-K: blockIdx.x = K-chunk (0..3, 256 deep), bn=0 (N=128),
//         writes fp32 partial to O1 + chunk*(M*128). No alpha/bias.
// ===========================================================================
#define TBKF 16
#define T_A_BYTES (128 * TBKF * 4)      // 8192
#define T_STG     (2 * T_A_BYTES)       // 16384
#define TNSTG 4
#define TF_DSMEM (TNSTG * T_STG)        // 65536

__device__ __forceinline__ uint32_t lde(const uint32_t* t, int row, int k) {
    int g = k >> 2;
    return t[row * 16 + (((g ^ ((row >> 1) & 3)) << 2) | (k & 3))];
}

__device__ __forceinline__ void load_stage_tf(
    uint32_t sbase, int stage, const float* __restrict__ A,
    const float* __restrict__ B, int bm, int bn, int k0, int K, int tid)
{
    uint32_t sa = sbase + stage * T_STG;
    uint32_t sb = sa + T_A_BYTES;
    int row = tid >> 1;
    int g0 = (tid & 1) * 2;
#pragma unroll
    for (int j = 0; j < 2; j++) {
        int g = g0 + j;
        uint32_t so = (uint32_t)(row * 64 + ((g ^ ((row >> 1) & 3)) << 4));
        cp16(sa + so, A + (long)(bm + row) * K + k0 + g * 4);
        cp16(sb + so, B + (long)(bn + row) * K + k0 + g * 4);
    }
}

template<int MODE>
__global__ void __launch_bounds__(256) gemm_tf(
    const float* __restrict__ A, const float* __restrict__ B,
    const float* __restrict__ qb, const float* __restrict__ kb,
    float* __restrict__ O1, float* __restrict__ Qf, float* __restrict__ Kf,
    int M, int N, int K, float alpha, long sA, long sB, long sC)
{
    extern __shared__ __align__(16) char dsm[];

    int bn;
    int kof = 0;
    int KT;
    if (MODE == 4) {
        bn = 0;
        kof = blockIdx.x * 256;          // K-chunk base
        KT = 256 / TBKF;                 // 16
        O1 += (long)blockIdx.x * ((long)M * 128);
    } else {
        A += (long)blockIdx.z * sA;
        B += (long)blockIdx.z * sB;
        O1 += (long)blockIdx.z * sC;
        bn = blockIdx.x * 128;
        KT = K / TBKF;
    }

    const int tid  = threadIdx.x;
    const int wid  = tid >> 5;
    const int lane = tid & 31;
    const int wm   = wid & 1;
    const int wn   = wid >> 1;
    const int bm = blockIdx.y * 128;

    uint32_t sbase = smem_u32(dsm);

    float acc[4][4][4];
#pragma unroll
    for (int i = 0; i < 4; i++)
#pragma unroll
        for (int j = 0; j < 4; j++)
#pragma unroll
            for (int r = 0; r < 4; r++) acc[i][j][r] = 0.f;

#pragma unroll
    for (int s = 0; s < TNSTG - 1; s++) {
        if (s < KT) load_stage_tf(sbase, s, A, B, bm, bn, kof + s * TBKF, K, tid);
        asm volatile("cp.async.commit_group;" ::: "memory");
    }

    const int lr = lane >> 2;
    const int lk = lane & 3;

    for (int kt = 0; kt < KT; kt++) {
        __syncthreads();
        if (kt + 3 < KT)
            load_stage_tf(sbase, (kt + 3) & 3, A, B, bm, bn, kof + (kt + 3) * TBKF, K, tid);
        asm volatile("cp.async.commit_group;" ::: "memory");
        asm volatile("cp.async.wait_group 3;" ::: "memory");
        __syncthreads();

        const uint32_t* sa = (const uint32_t*)(dsm + (size_t)(kt & 3) * T_STG);
        const uint32_t* sb = sa + 128 * TBKF;

#pragma unroll
        for (int ks = 0; ks < 2; ks++) {
            int kbase = ks * 8;
            uint32_t ah[4][4], al[4][4], bh[4][2], bl[4][2];
#pragma unroll
            for (int mf = 0; mf < 4; mf++) {
                int r0 = wm * 64 + mf * 16 + lr;
                split_tf32(lde(sa, r0,     kbase + lk),     ah[mf][0], al[mf][0]);
                split_tf32(lde(sa, r0 + 8, kbase + lk),     ah[mf][1], al[mf][1]);
                split_tf32(lde(sa, r0,     kbase + lk + 4), ah[mf][2], al[mf][2]);
                split_tf32(lde(sa, r0 + 8, kbase + lk + 4), ah[mf][3], al[mf][3]);
            }
#pragma unroll
            for (int nf = 0; nf < 4; nf++) {
                int n0 = wn * 32 + nf * 8 + lr;
                split_tf32(lde(sb, n0, kbase + lk),     bh[nf][0], bl[nf][0]);
                split_tf32(lde(sb, n0, kbase + lk + 4), bh[nf][1], bl[nf][1]);
            }
#pragma unroll
            for (int mf = 0; mf < 4; mf++)
#pragma unroll
                for (int nf = 0; nf < 4; nf++)
                    mma1688(acc[mf][nf], al[mf], bh[nf]);
#pragma unroll
            for (int mf = 0; mf < 4; mf++)
#pragma unroll
                for (int nf = 0; nf < 4; nf++)
                    mma1688(acc[mf][nf], ah[mf], bl[nf]);
#pragma unroll
            for (int mf = 0; mf < 4; mf++)
#pragma unroll
                for (int nf = 0; nf < 4; nf++)
                    mma1688(acc[mf][nf], ah[mf], bh[nf]);
        }
    }

#pragma unroll
    for (int mf = 0; mf < 4; mf++) {
        int r0 = bm + wm * 64 + mf * 16 + lr;
#pragma unroll
        for (int nf = 0; nf < 4; nf++) {
            int c0 = bn + wn * 32 + nf * 8 + lk * 2;
#pragma unroll
            for (int h = 0; h < 2; h++) {
                int row = r0 + h * 8;
                float vx = acc[mf][nf][2 * h + 0];
                float vy = acc[mf][nf][2 * h + 1];
                if (MODE == 0) {
                    vx *= alpha; vy *= alpha;
                    *(float2*)(O1 + (long)row * N + c0) = make_float2(vx, vy);
                } else { // MODE 4: fp32 partial, N=128 row pitch
                    *(float2*)(O1 + (long)row * 128 + c0) = make_float2(vx, vy);
                }
            }
        }
    }
}

// Deterministic split-K reduce for QK: sum 4 partials in fixed order + bias.
__global__ void __launch_bounds__(256) qk_reduce(
    const float* __restrict__ part, const float* __restrict__ qb,
    const float* __restrict__ kb, float* __restrict__ Qf, float* __restrict__ Kf)
{
    long i = (long)blockIdx.x * 256 + threadIdx.x;   // 0 .. 1048575
    long row = i >> 7;
    int col = (int)(i & 127);
    float s = part[i];
    s += part[i + 1048576L];
    s += part[i + 2097152L];
    s += part[i + 3145728L];
    if (col < 64) Qf[row * 64 + col] = s + qb[col];
    else          Kf[row * 64 + (col - 64)] = s + kb[col - 64];
}

// ---------------------------------------------------------------------------
// Weight splits: fp32 -> bf16 hi/lo, one fused launch (8 jobs, guarded)
// ---------------------------------------------------------------------------
struct SplitJob { const float* src; __nv_bfloat16* h; __nv_bfloat16* l; long n; };
struct SplitJobs8 { SplitJob j[8]; };

__global__ void __launch_bounds__(256) split8(SplitJobs8 jobs)
{
    const SplitJob jb = jobs.j[blockIdx.y];
    long i = ((long)blockIdx.x * 256 + threadIdx.x) * 2;
    if (i < jb.n) bpair_store(jb.h, jb.l, i, jb.src[i], jb.src[i + 1]);
}

__global__ void __launch_bounds__(256) concat_qk(
    const float* __restrict__ q, const float* __restrict__ k, float* __restrict__ o)
{
    int i = blockIdx.x * 256 + threadIdx.x;   // n = 131072
    o[i] = (i < 65536) ? q[i] : k[i - 65536];
}

// ---------------------------------------------------------------------------
// Fused RMSNorm + token-shift mixing.
// ---------------------------------------------------------------------------
template<int WRITE_H>
__global__ void __launch_bounds__(256) norm_mix_kernel(
    const float* __restrict__ x, const float* __restrict__ w,
    const float* __restrict__ mA, const float* __restrict__ mB,
    __nv_bfloat16* __restrict__ oAh, __nv_bfloat16* __restrict__ oAl,
    __nv_bfloat16* __restrict__ oBh, __nv_bfloat16* __restrict__ oBl,
    float* __restrict__ hF, __nv_bfloat16* __restrict__ hbH,
    __nv_bfloat16* __restrict__ hbL)
{
    long row = blockIdx.x;
    long prev = ((row & (S_LEN - 1)) == 0) ? row : row - 1;
    int tid = threadIdx.x;
    const float* xc = x + row * D_DIM;
    const float* xp = x + prev * D_DIM;

    float c[4], p[4];
    float sc_ = 0.f, sp_ = 0.f;
#pragma unroll
    for (int d = 0; d < 4; d++) {
        c[d] = xc[tid + d * 256];
        p[d] = xp[tid + d * 256];
        sc_ += c[d] * c[d];
        sp_ += p[d] * p[d];
    }
#pragma unroll
    for (int o = 16; o > 0; o >>= 1) {
        sc_ += __shfl_xor_sync(0xffffffffu, sc_, o);
        sp_ += __shfl_xor_sync(0xffffffffu, sp_, o);
    }

    __shared__ float redc[8], redp[8];
    __shared__ float s_invc, s_invp;
    if ((tid & 31) == 0) { redc[tid >> 5] = sc_; redp[tid >> 5] = sp_; }
    __syncthreads();
    if (tid == 0) {
        float tc = 0.f, tp = 0.f;
#pragma unroll
        for (int i = 0; i < 8; i++) { tc += redc[i]; tp += redp[i]; }
        s_invc = 1.0f / (sqrtf(tc / (float)D_DIM) + 1e-8f);
        s_invp = 1.0f / (sqrtf(tp / (float)D_DIM) + 1e-8f);
    }
    __syncthreads();
    float invc = s_invc, invp = s_invp;

#pragma unroll
    for (int d = 0; d < 4; d++) {
        int cc = tid + d * 256;
        long ci = row * D_DIM + cc;
        float nc = w[cc] * c[d] * invc;
        float np = w[cc] * p[d] * invp;
        float a = mA[cc], b = mB[cc];
        bsplit_store(oAh, oAl, ci, nc * a + np * (1.f - a));
        bsplit_store(oBh, oBl, ci, nc * b + np * (1.f - b));
        if (WRITE_H) {
            hF[ci] = nc;
            bsplit_store(hbH, hbL, ci, nc);
        }
    }
}

// ---------------------------------------------------------------------------
// Sparse attention: chunked top-32, softmax, attn@V -> bf16 pair out.
// ---------------------------------------------------------------------------
__global__ void __launch_bounds__(256) sparse_attn_kernel(
    const float* __restrict__ scores, const float* __restrict__ V,
    __nv_bfloat16* __restrict__ oh, __nv_bfloat16* __restrict__ ol)
{
    __shared__ float sc[S_LEN];
    __shared__ float cmax[128];
    __shared__ float selV[TOPK];
    __shared__ int   selI[TOPK];
    __shared__ float wsel[TOPK];

    long row = blockIdx.x;
    long b = row >> 12;
    int tid = threadIdx.x;
    int lane = tid & 31;

    const float* srow = scores + row * S_LEN;
    for (int i = tid; i < S_LEN; i += 256) sc[i] = srow[i];
    __syncthreads();

    if (tid < 128) {
        float m = NEG_INF;
#pragma unroll 8
        for (int i = 0; i < 32; i++) m = fmaxf(m, sc[tid * 32 + i]);
        cmax[tid] = m;
    }
    __syncthreads();

    if (tid < 32) {
        for (int it = 0; it < TOPK; it++) {
            float bv = NEG_INF; int bc = 0;
#pragma unroll
            for (int j = 0; j < 4; j++) {
                int c = lane * 4 + j;
                float v = cmax[c];
                if (v > bv) { bv = v; bc = c; }
            }
#pragma unroll
            for (int o = 16; o > 0; o >>= 1) {
                float ov = __shfl_down_sync(0xffffffffu, bv, o);
                int   oc = __shfl_down_sync(0xffffffffu, bc, o);
                if (ov > bv || (ov == bv && oc < bc)) { bv = ov; bc = oc; }
            }
            bc = __shfl_sync(0xffffffffu, bc, 0);

            float v = sc[bc * 32 + lane];
            float mv = v; int mi = lane;
#pragma unroll
            for (int o = 16; o > 0; o >>= 1) {
                float ov = __shfl_down_sync(0xffffffffu, mv, o);
                int   oi = __shfl_down_sync(0xffffffffu, mi, o);
                if (ov > mv || (ov == mv && oi < mi)) { mv = ov; mi = oi; }
            }
            mv = __shfl_sync(0xffffffffu, mv, 0);
            mi = __shfl_sync(0xffffffffu, mi, 0);

            if (lane == mi) { sc[bc * 32 + lane] = NEG_INF; v = NEG_INF; }
            if (lane == 0) { selV[it] = mv; selI[it] = bc * 32 + mi; }

            float nm = v;
#pragma unroll
            for (int o = 16; o > 0; o >>= 1)
                nm = fmaxf(nm, __shfl_down_sync(0xffffffffu, nm, o));
            if (lane == 0) cmax[bc] = nm;
        }
        float m = __shfl_sync(0xffffffffu, selV[0], 0);
        float e = expf(selV[lane] - m);
        float s = e;
#pragma unroll
        for (int o = 16; o > 0; o >>= 1) s += __shfl_xor_sync(0xffffffffu, s, o);
        wsel[lane] = e / s;
    }
    __syncthreads();

    float acc[4] = {0.f, 0.f, 0.f, 0.f};
    const float* Vb = V + b * (long)S_LEN * D_DIM;
#pragma unroll 1
    for (int j = 0; j < TOPK; j++) {
        float w = wsel[j];
        const float* vr = Vb + (long)selI[j] * D_DIM;
#pragma unroll
        for (int d = 0; d < 4; d++) acc[d] += w * vr[tid + d * 256];
    }
#pragma unroll
    for (int d = 0; d < 4; d++)
        bsplit_store(oh, ol, row * D_DIM + tid + d * 256, acc[d]);
}

// ---------------------------------------------------------------------------
// Host launchers
// ---------------------------------------------------------------------------
typedef __nv_bfloat16 bf16;

static void launch_bf(cudaStream_t st, int mode,
    const bf16* Ah, const bf16* Al, const bf16* Bh, const bf16* Bl,
    const float* b1, const float* e1, const float* e2,
    float* Of, bf16* Oh, bf16* Ol, int M, int N, int K,
    const bf16* A2h = nullptr, const bf16* A2l = nullptr,
    const bf16* B2h = nullptr, const bf16* B2l = nullptr, float* Of2 = nullptr,
    const bf16* A3h = nullptr, const bf16* A3l = nullptr,
    const bf16* B3h = nullptr, const bf16* B3l = nullptr, float* Of3 = nullptr,
    const float* b3 = nullptr, int gx = -1, int gz = 1)
{
    dim3 grid(gx < 0 ? N / 128 : gx, M / 128, gz);
    switch (mode) {
    case 0: gemm_bf<0><<<grid, 256, BF_DSMEM, st>>>(Ah,Al,Bh,Bl,b1,e1,e2,Of,Oh,Ol,M,N,K,A2h,A2l,B2h,B2l,Of2,A3h,A3l,B3h,B3l,Of3,b3); break;
    case 1: gemm_bf<1><<<grid, 256, BF_DSMEM, st>>>(Ah,Al,Bh,Bl,b1,e1,e2,Of,Oh,Ol,M,N,K,A2h,A2l,B2h,B2l,Of2,A3h,A3l,B3h,B3l,Of3,b3); break;
    case 3: gemm_bf<3><<<grid, 256, BF_DSMEM, st>>>(Ah,Al,Bh,Bl,b1,e1,e2,Of,Oh,Ol,M,N,K,A2h,A2l,B2h,B2l,Of2,A3h,A3l,B3h,B3l,Of3,b3); break;
    case 4: gemm_bf<4><<<grid, 256, BF_DSMEM, st>>>(Ah,Al,Bh,Bl,b1,e1,e2,Of,Oh,Ol,M,N,K,A2h,A2l,B2h,B2l,Of2,A3h,A3l,B3h,B3l,Of3,b3); break;
    case 5: gemm_bf<5><<<grid, 256, BF_DSMEM, st>>>(Ah,Al,Bh,Bl,b1,e1,e2,Of,Oh,Ol,M,N,K,A2h,A2l,B2h,B2l,Of2,A3h,A3l,B3h,B3l,Of3,b3); break;
    default: gemm_bf<6><<<grid, 256, BF_DSMEM, st>>>(Ah,Al,Bh,Bl,b1,e1,e2,Of,Oh,Ol,M,N,K,A2h,A2l,B2h,B2l,Of2,A3h,A3l,B3h,B3l,Of3,b3); break;
    }
}

extern "C" void kernel_launch(void* const* d_in, const int* in_sizes, int n_in,
                              void* d_out, int out_size)
{
    const float* x         = (const float*)d_in[0];
    const float* norm1_w   = (const float*)d_in[1];
    const float* tm_mix_v  = (const float*)d_in[3];
    const float* tm_mix_r  = (const float*)d_in[4];
    const float* tm_value_w  = (const float*)d_in[6];
    const float* tm_recept_w = (const float*)d_in[7];
    const float* tm_out_w    = (const float*)d_in[8];
    const float* sa_q_w    = (const float*)d_in[9];
    const float* sa_q_b    = (const float*)d_in[10];
    const float* sa_k_w    = (const float*)d_in[11];
    const float* sa_k_b    = (const float*)d_in[12];
    const float* sa_v_w    = (const float*)d_in[13];
    const float* sa_v_b    = (const float*)d_in[14];
    const float* sa_o_w    = (const float*)d_in[15];
    const float* sa_o_b    = (const float*)d_in[16];
    const float* norm2_w   = (const float*)d_in[17];
    const float* cm_mix_k  = (const float*)d_in[18];
    const float* cm_mix_r  = (const float*)d_in[19];
    const float* cm_key_w    = (const float*)d_in[20];
    const float* cm_recept_w = (const float*)d_in[21];
    const float* cm_value_w  = (const float*)d_in[22];
    float* out = (float*)d_out;

    cudaFuncSetAttribute(gemm_bf<0>, cudaFuncAttributeMaxDynamicSharedMemorySize, BF_DSMEM);
    cudaFuncSetAttribute(gemm_bf<1>, cudaFuncAttributeMaxDynamicSharedMemorySize, BF_DSMEM);
    cudaFuncSetAttribute(gemm_bf<3>, cudaFuncAttributeMaxDynamicSharedMemorySize, BF_DSMEM);
    cudaFuncSetAttribute(gemm_bf<4>, cudaFuncAttributeMaxDynamicSharedMemorySize, BF_DSMEM);
    cudaFuncSetAttribute(gemm_bf<5>, cudaFuncAttributeMaxDynamicSharedMemorySize, BF_DSMEM);
    cudaFuncSetAttribute(gemm_bf<6>, cudaFuncAttributeMaxDynamicSharedMemorySize, BF_DSMEM);
    cudaFuncSetAttribute(gemm_tf<0>, cudaFuncAttributeMaxDynamicSharedMemorySize, TF_DSMEM);
    cudaFuncSetAttribute(gemm_tf<4>, cudaFuncAttributeMaxDynamicSharedMemorySize, TF_DSMEM);

    float* sp = nullptr;
    cudaGetSymbolAddress((void**)&sp, g_scratch);

    float* hF   = sp + O_HF;
    float* Vtm  = sp + O_VTM;
    float* Rtm  = sp + O_RTM;
    float* Vv   = sp + O_VV;
    float* x2   = sp + O_X2;
    float* R2   = sp + O_R2;
    float* Qf   = sp + O_Q;
    float* Kf   = sp + O_K;
    float* wQKf = sp + O_WQKF;
    float* SCo  = sp + O_SC;
    float* qkP  = sp + O_QKP;

    bf16* hbH = (bf16*)(sp + O_BHB); bf16* hbL = (bf16*)(sp + O_BHL);
    bf16* xvH = (bf16*)(sp + O_XVH); bf16* xvL = (bf16*)(sp + O_XVL);
    bf16* xrH = (bf16*)(sp + O_XRH); bf16* xrL = (bf16*)(sp + O_XRL);
    bf16* atH = (bf16*)(sp + O_ATH); bf16* atL = (bf16*)(sp + O_ATL);
    bf16* rkH = (bf16*)(sp + O_RKH); bf16* rkL = (bf16*)(sp + O_RKL);
    bf16* KcH = (bf16*)(sp + O_KCH); bf16* KcL = (bf16*)(sp + O_KCL);

    bf16* wTMVh = (bf16*)(sp + O_WTMV); bf16* wTMVl = wTMVh + 1048576L;
    bf16* wTMRh = (bf16*)(sp + O_WTMR); bf16* wTMRl = wTMRh + 1048576L;
    bf16* wSAVh = (bf16*)(sp + O_WSAV); bf16* wSAVl = wSAVh + 1048576L;
    bf16* wSAOh = (bf16*)(sp + O_WSAO); bf16* wSAOl = wSAOh + 1048576L;
    bf16* wTMOh = (bf16*)(sp + O_WTMO); bf16* wTMOl = wTMOh + 1048576L;
    bf16* wCMRh = (bf16*)(sp + O_WCMR); bf16* wCMRl = wCMRh + 1048576L;
    bf16* wCMKh = (bf16*)(sp + O_WCMK); bf16* wCMKl = wCMKh + 4194304L;
    bf16* wCMVh = (bf16*)(sp + O_WCMV); bf16* wCMVl = wCMVh + 4194304L;

    // side stream + fork/join events (created per call; host-side only)
    cudaStream_t s1;
    cudaStreamCreateWithFlags(&s1, cudaStreamNonBlocking);
    cudaEvent_t eRoot, eSplit, eNM, eSc;
    cudaEventCreateWithFlags(&eRoot,  cudaEventDisableTiming);
    cudaEventCreateWithFlags(&eSplit, cudaEventDisableTiming);
    cudaEventCreateWithFlags(&eNM,    cudaEventDisableTiming);
    cudaEventCreateWithFlags(&eSc,    cudaEventDisableTiming);

    // fork s1 from main stream
    cudaEventRecord(eRoot, 0);
    cudaStreamWaitEvent(s1, eRoot, 0);

    // s1: weight splits + QK weight concat
    {
        SplitJobs8 s8;
        s8.j[0] = {tm_value_w,  wTMVh, wTMVl, 1048576L};
        s8.j[1] = {tm_recept_w, wTMRh, wTMRl, 1048576L};
        s8.j[2] = {sa_v_w,      wSAVh, wSAVl, 1048576L};
        s8.j[3] = {sa_o_w,      wSAOh, wSAOl, 1048576L};
        s8.j[4] = {tm_out_w,    wTMOh, wTMOl, 1048576L};
        s8.j[5] = {cm_recept_w, wCMRh, wCMRl, 1048576L};
        s8.j[6] = {cm_key_w,    wCMKh, wCMKl, 4194304L};
        s8.j[7] = {cm_value_w,  wCMVh, wCMVl, 4194304L};
        split8<<<dim3(8192, 8, 1), 256, 0, s1>>>(s8);
        concat_qk<<<512, 256, 0, s1>>>(sa_q_w, sa_k_w, wQKf);
        cudaEventRecord(eSplit, s1);
    }

    // main: norm_mix1 (independent of splits)
    norm_mix_kernel<1><<<NROWS, 256, 0, 0>>>(x, norm1_w, tm_mix_v, tm_mix_r,
                                             xvH, xvL, xrH, xrL, hF, hbH, hbL);
    cudaEventRecord(eNM, 0);

    // s1: QK projection split-K x4 -> reduce -> scores; concurrent with
    // the main-stream triple GEMM below.
    cudaStreamWaitEvent(s1, eNM, 0);
    {
        dim3 g(4, NROWS / 128, 1);
        gemm_tf<4><<<g, 256, TF_DSMEM, s1>>>(hF, wQKf, nullptr, nullptr,
                                             qkP, nullptr, nullptr, NROWS, 128, D_DIM,
                                             1.f, 0, 0, 0);
        qk_reduce<<<4096, 256, 0, s1>>>(qkP, sa_q_b, sa_k_b, Qf, Kf);
    }
    {
        dim3 g(S_LEN / 128, S_LEN / 128, B_SZ);
        gemm_tf<0><<<g, 256, TF_DSMEM, s1>>>(Qf, Kf, nullptr, nullptr,
                                             SCo, nullptr, nullptr, S_LEN, S_LEN, A_DIM,
                                             0.125f, (long)S_LEN * A_DIM,
                                             (long)S_LEN * A_DIM, (long)S_LEN * S_LEN);
    }
    cudaEventRecord(eSc, s1);

    // main: triple merged GEMM (needs weight splits)
    cudaStreamWaitEvent(0, eSplit, 0);
    launch_bf(0, 0, xvH, xvL, wTMVh, wTMVl, nullptr, nullptr, nullptr,
              Vtm, nullptr, nullptr, NROWS, D_DIM, D_DIM,
              xrH, xrL, wTMRh, wTMRl, Rtm,
              hbH, hbL, wSAVh, wSAVl, Vv, sa_v_b, -1, 3);

    // main: join scores chain, then sparse attention (needs SCo + Vv)
    cudaStreamWaitEvent(0, eSc, 0);
    sparse_attn_kernel<<<NROWS, 256, 0, 0>>>(SCo, Vv, atH, atL);

    // rkv = sigmoid(Rtm) * (attn@W_o + b_o + Vtm) -> bf16 pair
    launch_bf(0, 3, atH, atL, wSAOh, wSAOl, sa_o_b, Rtm, Vtm,
              nullptr, rkH, rkL, NROWS, D_DIM, D_DIM);

    // x2 = x + rkv @ W_out
    launch_bf(0, 4, rkH, rkL, wTMOh, wTMOl, nullptr, x, nullptr,
              x2, nullptr, nullptr, NROWS, D_DIM, D_DIM);

    // --- channel-mix branch ---
    norm_mix_kernel<0><<<NROWS, 256, 0, 0>>>(x2, norm2_w, cm_mix_k, cm_mix_r,
                                             xvH, xvL, xrH, xrL,
                                             nullptr, nullptr, nullptr);

    // merged: blocks x<32 -> Kc = relu(xk2@W_k)^2 (bf16 pair), x>=32 -> R2
    launch_bf(0, 6, xvH, xvL, wCMKh, wCMKl, nullptr, nullptr, nullptr,
              nullptr, KcH, KcL, NROWS, DI_DIM, D_DIM,
              xrH, xrL, wCMRh, wCMRl, R2,
              nullptr, nullptr, nullptr, nullptr, nullptr, nullptr, 40, 1);

    // out = x2 + sigmoid(R2) * (Kc @ W_v)
    launch_bf(0, 5, KcH, KcL, wCMVh, wCMVl, nullptr, x2, R2,
              out, nullptr, nullptr, NROWS, D_DIM, DI_DIM);

    cudaEventDestroy(eRoot);
    cudaEventDestroy(eSplit);
    cudaEventDestroy(eNM);
    cudaEventDestroy(eSc);
    cudaStreamDestroy(s1);
}